// round 12
// baseline (speedup 1.0000x reference)
#include <cuda_runtime.h>
#include <cuda_bf16.h>
#include <math.h>
#include <stdint.h>
typedef unsigned long long ull;

#define NS   128
#define SEQ  8192
#define OUTD 1000

// ---------------- device scratch ----------------
__device__ float g_PT[(size_t)2 * NS * NS];
__device__ float g_cs[(size_t)3 * SEQ * NS];
__device__ float g_U[3 * 64 * NS];
__device__ float g_B[3 * 64 * NS];
__device__ float g_ctxp[(size_t)8 * SEQ * NS];
__device__ float g_attn_fb[(size_t)SEQ * SEQ];
__device__ float g_tmax[(size_t)128 * SEQ];
__device__ float g_tsum[(size_t)128 * SEQ];
__device__ float g_RM[SEQ];
__device__ float g_RSI[SEQ];
__device__ __align__(256) __nv_bfloat16 g_qh[(size_t)SEQ * NS], g_ql[(size_t)SEQ * NS];
__device__ __align__(256) __nv_bfloat16 g_kh[(size_t)SEQ * NS], g_kl[(size_t)SEQ * NS];
__device__ __align__(256) __nv_bfloat16 g_vth[(size_t)NS * SEQ], g_vtl[(size_t)NS * SEQ];
__device__ __align__(256) __nv_bfloat16 g_ch[(size_t)SEQ * NS], g_clo[(size_t)SEQ * NS];
__device__ __align__(256) __nv_bfloat16 g_wph[(size_t)1024 * NS], g_wpl[(size_t)1024 * NS];
__device__ __align__(256) __nv_bfloat16 g_PTth[(size_t)129 * NS * NS], g_PTtl[(size_t)129 * NS * NS];
__device__ __align__(256) __nv_bfloat16 g_QTth[(size_t)64 * NS * NS],  g_QTtl[(size_t)64 * NS * NS];
__device__ __align__(256) __nv_bfloat16 g_Kth[NS * NS], g_Ktl[NS * NS];

// ---------------- PTX helpers ----------------
__device__ __forceinline__ uint32_t smem_u32(const void* p) {
  uint32_t a;
  asm("{ .reg .u64 t; cvta.to.shared.u64 t, %1; cvt.u32.u64 %0, t; }" : "=r"(a) : "l"(p));
  return a;
}
__device__ __forceinline__ void cp16(uint32_t d, const void* s) {
  asm volatile("cp.async.cg.shared.global [%0], [%1], 16;" ::"r"(d),"l"(s):"memory");
}
#define CP_COMMIT() asm volatile("cp.async.commit_group;" :::"memory")
#define CP_WAIT0()  asm volatile("cp.async.wait_group 0;" :::"memory")
#define CP_WAIT1()  asm volatile("cp.async.wait_group 1;" :::"memory")
__device__ __forceinline__ void sts32(uint32_t a, uint32_t v) {
  asm volatile("st.shared.b32 [%0], %1;" ::"r"(a),"r"(v):"memory");
}
__device__ __forceinline__ void ldm4(uint32_t a, uint32_t f[4]) {
  asm volatile("ldmatrix.sync.aligned.m8n8.x4.shared.b16 {%0,%1,%2,%3}, [%4];"
    : "=r"(f[0]),"=r"(f[1]),"=r"(f[2]),"=r"(f[3]) : "r"(a));
}
__device__ __forceinline__ void mma16816(float c[4], const uint32_t a[4], const uint32_t b0, const uint32_t b1) {
  asm volatile("mma.sync.aligned.m16n8k16.row.col.f32.bf16.bf16.f32 "
    "{%0,%1,%2,%3},{%4,%5,%6,%7},{%8,%9},{%0,%1,%2,%3};"
    : "+f"(c[0]),"+f"(c[1]),"+f"(c[2]),"+f"(c[3])
    : "r"(a[0]),"r"(a[1]),"r"(a[2]),"r"(a[3]),"r"(b0),"r"(b1));
}

// padded bf16 tile: 128 rows x 136 cols
#define TPAD 136
#define TILE_B (128 * TPAD * 2)
#define OAH 0u
#define OAL (1u * TILE_B)
#define OBH (2u * TILE_B)
#define OBL (3u * TILE_B)
#define OB2 (2u * TILE_B)
#define GEMM3_SM (3 * TILE_B)          // 104,448 B -> 2 CTAs/SM
#define SCAN2_SM (4 * TILE_B + 512)
#define POW_SM   (2 * 128 * 132 * 4)

// 256-thread tile loader
__device__ __forceinline__ void load_tile(uint32_t sbt, const __nv_bfloat16* src, int stride, int tid) {
#pragma unroll
  for (int t = tid; t < 2048; t += 256) {
    int row = t >> 4, col = (t & 15) << 3;
    cp16(sbt + row * (TPAD * 2) + (col << 1), src + (size_t)row * stride + col);
  }
}

// 8-warp gemm pass: warp = 32m x 64n
__device__ __forceinline__ void gemm_pass(uint32_t sA, uint32_t sB, int lane, int wm, int wn,
                                          float acc[2][8][4]) {
#pragma unroll
  for (int ks = 0; ks < 8; ks++) {
    int kb = ks * 16;
    uint32_t afr[2][4];
#pragma unroll
    for (int mt = 0; mt < 2; mt++) {
      uint32_t addr = sA + (uint32_t)(((wm * 32 + mt * 16 + (lane & 15)) * TPAD + kb + ((lane >> 4) << 3)) << 1);
      ldm4(addr, afr[mt]);
    }
#pragma unroll
    for (int np = 0; np < 4; np++) {
      uint32_t f[4];
      uint32_t addr = sB + (uint32_t)(((wn * 64 + np * 16 + (lane & 7) + ((lane >> 4) << 3)) * TPAD + kb + (lane & 8)) << 1);
      ldm4(addr, f);
#pragma unroll
      for (int mt = 0; mt < 2; mt++) {
        mma16816(acc[mt][np * 2],     afr[mt], f[0], f[1]);
        mma16816(acc[mt][np * 2 + 1], afr[mt], f[2], f[3]);
      }
    }
  }
}
__device__ __forceinline__ void gemm3v(uint32_t aH, uint32_t aL, uint32_t bH, uint32_t bL,
                                       int lane, int wm, int wn, float acc[2][8][4]) {
  gemm_pass(aH, bH, lane, wm, wn, acc);
  gemm_pass(aH, bL, lane, wm, wn, acc);
  gemm_pass(aL, bH, lane, wm, wn, acc);
}

__device__ __forceinline__ void split16(float x, __nv_bfloat16& h, __nv_bfloat16& l) {
  h = __float2bfloat16(x);
  l = __float2bfloat16(x - __bfloat162float(h));
}
__device__ __forceinline__ uint32_t packbf(__nv_bfloat16 lo_e, __nv_bfloat16 hi_e) {
  return ((uint32_t)__bfloat16_as_ushort(hi_e) << 16) | __bfloat16_as_ushort(lo_e);
}
__device__ __forceinline__ void split_store2(uint32_t sb, uint32_t offH, uint32_t offL,
                                             int r, int c0, float x0, float x1) {
  __nv_bfloat16 h0, l0, h1, l1;
  split16(x0, h0, l0); split16(x1, h1, l1);
  uint32_t off = (uint32_t)(r * TPAD + c0) << 1;
  sts32(sb + offH + off, packbf(h0, h1));
  sts32(sb + offL + off, packbf(l0, l1));
}

// ---------------- f32x2 mm (k_powers only) ----------------
__device__ __forceinline__ void mm128(const float* As, const float* Bs, int tx, int ty, ull acc[8][4]) {
#pragma unroll 4
  for (int kk = 0; kk < 128; kk++) {
    ull bp[4];
#pragma unroll
    for (int j = 0; j < 4; j++) bp[j] = *(const ull*)&Bs[kk*132 + tx*8 + j*2];
#pragma unroll
    for (int i = 0; i < 8; i++) {
      float a = As[(ty*8+i)*132 + kk];
      ull ap; asm("mov.b64 %0,{%1,%1};" : "=l"(ap) : "f"(a));
#pragma unroll
      for (int j = 0; j < 4; j++)
        asm("fma.rn.f32x2 %0,%1,%2,%0;" : "+l"(acc[i][j]) : "l"(ap), "l"(bp[j]));
    }
  }
}
__device__ __forceinline__ float2 upk(ull p) {
  float2 r; asm("mov.b64 {%0,%1}, %2;" : "=f"(r.x), "=f"(r.y) : "l"(p)); return r;
}

__global__ void k_init(const float* __restrict__ GA) {
  int m = blockIdx.x, n = threadIdx.x;
  g_PT[m*NS+n] = (m==n) ? 1.f : 0.f;
  g_PT[NS*NS + m*NS + n] = GA[n*NS + m];
}

__global__ void k_prep_small(const float* __restrict__ GB) {
  int tid = threadIdx.x;
  __nv_bfloat16 one = __float2bfloat16(1.f), zero = __float2bfloat16(0.f);
  for (int l = tid; l < 8192; l += 256) {
    int n = l >> 6, k0 = (l & 63) * 2;
    uint32_t h = 0;
    if (n == k0) h = packbf(one, zero);
    else if (n == k0 + 1) h = packbf(zero, one);
    *(uint32_t*)(g_QTth + n*128 + k0) = h;
    *(uint32_t*)(g_QTtl + n*128 + k0) = 0;
  }
  if (tid < 128) {
    __nv_bfloat16 h, l;
    split16(GB[tid], h, l);
    g_Kth[tid*128 + 0] = h;
    g_Ktl[tid*128 + 0] = l;
  }
}

__global__ __launch_bounds__(256) void k_powers_f(const float* __restrict__ GB) {
  extern __shared__ float sm[];
  float* R = sm;
  float* G = sm + 128*132;
  int b = blockIdx.x, tid = threadIdx.x, tx = tid & 15, ty = tid >> 4;
  int e; __nv_bfloat16 *dh, *dl;
  if (b < 128) { e = b + 1; dh = g_PTth + (size_t)(b+1)*NS*NS; dl = g_PTtl + (size_t)(b+1)*NS*NS; }
  else { int p = b - 127; e = p << 7; dh = g_QTth + (size_t)p*NS*NS; dl = g_QTtl + (size_t)p*NS*NS; }
  const float* GAT = g_PT + NS*NS;
  for (int l = tid; l < NS*NS; l += 256) {
    int r = l >> 7, c = l & 127;
    float v = GAT[l];
    G[r*132+c] = v; R[r*132+c] = v;
  }
  __syncthreads();
  int msb = 31 - __clz(e);
  for (int bit = msb - 1; bit >= 0; bit--) {
    {
      ull acc[8][4] = {};
      mm128(R, R, tx, ty, acc);
      __syncthreads();
#pragma unroll
      for (int i = 0; i < 8; i++)
#pragma unroll
        for (int j = 0; j < 4; j++) {
          float2 v = upk(acc[i][j]);
          R[(ty*8+i)*132 + tx*8 + j*2] = v.x;
          R[(ty*8+i)*132 + tx*8 + j*2 + 1] = v.y;
        }
      __syncthreads();
    }
    if ((e >> bit) & 1) {
      ull acc[8][4] = {};
      mm128(R, G, tx, ty, acc);
      __syncthreads();
#pragma unroll
      for (int i = 0; i < 8; i++)
#pragma unroll
        for (int j = 0; j < 4; j++) {
          float2 v = upk(acc[i][j]);
          R[(ty*8+i)*132 + tx*8 + j*2] = v.x;
          R[(ty*8+i)*132 + tx*8 + j*2 + 1] = v.y;
        }
      __syncthreads();
    }
  }
  for (int l = tid; l < 8192; l += 256) {
    int n = l >> 6, k0 = (l & 63) * 2;
    __nv_bfloat16 h0, l0, h1, l1;
    split16(R[k0*132 + n], h0, l0);
    split16(R[(k0+1)*132 + n], h1, l1);
    *(uint32_t*)(dh + (size_t)n*128 + k0) = packbf(h0, h1);
    *(uint32_t*)(dl + (size_t)n*128 + k0) = packbf(l0, l1);
  }
  if (b < 127 && tid < 128) {
    int n = tid;
    float acc = 0.f;
#pragma unroll 4
    for (int m = 0; m < 128; m++) acc = fmaf(R[m*132 + n], GB[m], acc);
    __nv_bfloat16 h, l;
    split16(acc, h, l);
    g_Kth[n*128 + (b+1)] = h;
    g_Ktl[n*128 + (b+1)] = l;
  }
}

// ---------------- scan GEMMs (unchanged R11) ----------------
__global__ __launch_bounds__(256) void k_localconv_h(const float* __restrict__ fq,
                                                     const float* __restrict__ fk,
                                                     const float* __restrict__ fv) {
  extern __shared__ char dsm[];
  uint32_t sb = smem_u32(dsm);
  float* fs = (float*)(dsm + 4*TILE_B);
  int ci = blockIdx.x, ch = blockIdx.y;
  const float* f = (ch == 0) ? fq : ((ch == 1) ? fk : fv);
  int tid = threadIdx.x, lane = tid & 31, wid = tid >> 5;
  int wm = wid & 3, wn = wid >> 2;
  load_tile(sb + OBH, g_Kth, 128, tid);
  load_tile(sb + OBL, g_Ktl, 128, tid);
  CP_COMMIT();
  if (tid < 128) fs[tid] = f[ci*128 + tid];
  __syncthreads();
  for (int l = tid; l < 8192; l += 256) {
    int r = l >> 6, c0 = (l & 63) * 2;
    float x0 = (c0 <= r) ? fs[r - c0] : 0.f;
    float x1 = (c0 + 1 <= r) ? fs[r - c0 - 1] : 0.f;
    split_store2(sb, OAH, OAL, r, c0, x0, x1);
  }
  CP_WAIT0();
  __syncthreads();
  float acc[2][8][4] = {};
  gemm3v(sb + OAH, sb + OAL, sb + OBH, sb + OBL, lane, wm, wn, acc);
  float* Cc = g_cs + ((size_t)ch*SEQ + (size_t)ci*128) * NS;
#pragma unroll
  for (int mt = 0; mt < 2; mt++) {
    int r0 = wm*32 + mt*16 + (lane >> 2);
#pragma unroll
    for (int nt = 0; nt < 8; nt++) {
      int gc = wn*64 + nt*8 + 2*(lane & 3);
      *(float2*)(Cc + (size_t)r0*NS + gc)     = make_float2(acc[mt][nt][0], acc[mt][nt][1]);
      *(float2*)(Cc + (size_t)(r0+8)*NS + gc) = make_float2(acc[mt][nt][2], acc[mt][nt][3]);
      if (r0 + 8 == 127)
        *(float2*)(g_U + (size_t)(ch*64 + ci)*NS + gc) = make_float2(acc[mt][nt][2], acc[mt][nt][3]);
    }
  }
}

__global__ void k_zeroB() {
  int i = blockIdx.x * 256 + threadIdx.x;
  if (i < 3*64*NS) g_B[i] = 0.f;
}

__global__ __launch_bounds__(256) void k_boundary_h() {
  extern __shared__ char dsm[];
  uint32_t sb = smem_u32(dsm);
  int p = blockIdx.x, rb = blockIdx.y;
  int tid = threadIdx.x, lane = tid & 31, wid = tid >> 5;
  int wm = wid & 3, wn = wid >> 2;
  load_tile(sb + OBH, g_QTth + (size_t)p*NS*NS, 128, tid);
  load_tile(sb + OBL, g_QTtl + (size_t)p*NS*NS, 128, tid);
  CP_COMMIT();
  for (int l = tid; l < 8192; l += 256) {
    int r = l >> 6, c0 = (l & 63) * 2;
    int gr = rb*128 + r;
    bool ok = (gr < 192) && ((gr & 63) >= p);
    float x0 = ok ? g_U[(size_t)(gr - p)*NS + c0] : 0.f;
    float x1 = ok ? g_U[(size_t)(gr - p)*NS + c0 + 1] : 0.f;
    split_store2(sb, OAH, OAL, r, c0, x0, x1);
  }
  CP_WAIT0();
  __syncthreads();
  float acc[2][8][4] = {};
  gemm3v(sb + OAH, sb + OAL, sb + OBH, sb + OBL, lane, wm, wn, acc);
#pragma unroll
  for (int mt = 0; mt < 2; mt++) {
    int r0 = wm*32 + mt*16 + (lane >> 2);
#pragma unroll
    for (int e2 = 0; e2 < 2; e2++) {
      int gr = rb*128 + r0 + e2*8;
      if (gr < 192 && (gr & 63) >= p) {
#pragma unroll
        for (int nt = 0; nt < 8; nt++) {
          int gc = wn*64 + nt*8 + 2*(lane & 3);
          atomicAdd(&g_B[(size_t)gr*NS + gc],     acc[mt][nt][e2*2]);
          atomicAdd(&g_B[(size_t)gr*NS + gc + 1], acc[mt][nt][e2*2 + 1]);
        }
      }
    }
  }
}

__global__ __launch_bounds__(256) void k_propagate_h() {
  extern __shared__ char dsm[];
  uint32_t sb = smem_u32(dsm);
  int r = blockIdx.x, rb = blockIdx.y;
  int tid = threadIdx.x, lane = tid & 31, wid = tid >> 5;
  int wm = wid & 3, wn = wid >> 2;
  load_tile(sb + OBH, g_PTth + (size_t)(r+1)*NS*NS, 128, tid);
  load_tile(sb + OBL, g_PTtl + (size_t)(r+1)*NS*NS, 128, tid);
  CP_COMMIT();
  for (int l = tid; l < 8192; l += 256) {
    int rr = l >> 6, c0 = (l & 63) * 2;
    int gr = rb*128 + rr;
    float x0 = (gr < 192) ? g_B[(size_t)gr*NS + c0] : 0.f;
    float x1 = (gr < 192) ? g_B[(size_t)gr*NS + c0 + 1] : 0.f;
    split_store2(sb, OAH, OAL, rr, c0, x0, x1);
  }
  CP_WAIT0();
  __syncthreads();
  float acc[2][8][4] = {};
  gemm3v(sb + OAH, sb + OAL, sb + OBH, sb + OBL, lane, wm, wn, acc);
#pragma unroll
  for (int mt = 0; mt < 2; mt++) {
    int r0 = wm*32 + mt*16 + (lane >> 2);
#pragma unroll
    for (int e2 = 0; e2 < 2; e2++) {
      int gr = rb*128 + r0 + e2*8;
      if (gr < 192 && (gr & 63) < 63) {
        int ch = gr >> 6, ic = (gr & 63) + 1;
        float* dst = &g_cs[((size_t)ch*SEQ + (size_t)ic*128 + r) * NS];
#pragma unroll
        for (int nt = 0; nt < 8; nt++) {
          int gc = wn*64 + nt*8 + 2*(lane & 3);
          dst[gc]     += acc[mt][nt][e2*2];
          dst[gc + 1] += acc[mt][nt][e2*2 + 1];
        }
      }
    }
  }
}

// ---------------- bf16 hi/lo preps ----------------
__global__ void k_prep_qk() {
  size_t idx = (size_t)blockIdx.x * 256 + threadIdx.x;
  float x = g_cs[idx];
  __nv_bfloat16 h, l;
  split16(x, h, l);
  size_t SN = (size_t)SEQ * NS;
  if (idx < SN) { g_qh[idx] = h; g_ql[idx] = l; }
  else          { g_kh[idx - SN] = h; g_kl[idx - SN] = l; }
}
__global__ void k_prep_vt() {
  __shared__ float t[32][33];
  int t0 = blockIdx.x * 32, n0 = blockIdx.y * 32;
  int tx = threadIdx.x, ty = threadIdx.y;
  const float* v = g_cs + (size_t)2 * SEQ * NS;
#pragma unroll
  for (int j = 0; j < 32; j += 8) t[ty+j][tx] = v[(size_t)(t0 + ty + j)*NS + n0 + tx];
  __syncthreads();
#pragma unroll
  for (int j = 0; j < 32; j += 8) {
    __nv_bfloat16 h, l;
    split16(t[tx][ty+j], h, l);
    size_t o = (size_t)(n0 + ty + j) * SEQ + t0 + tx;
    g_vth[o] = h; g_vtl[o] = l;
  }
}
__global__ void k_prep_wpt(const float* __restrict__ Wp) {
  __shared__ float t[32][33];
  int n0 = blockIdx.x * 32, k0 = blockIdx.y * 32;
  int tx = threadIdx.x, ty = threadIdx.y;
#pragma unroll
  for (int j = 0; j < 32; j += 8) {
    int n = n0 + tx;
    t[ty+j][tx] = (n < OUTD) ? Wp[(size_t)(k0 + ty + j)*OUTD + n] : 0.f;
  }
  __syncthreads();
#pragma unroll
  for (int j = 0; j < 32; j += 8) {
    __nv_bfloat16 h, l;
    split16(t[tx][ty+j], h, l);
    size_t o = (size_t)(n0 + ty + j) * NS + k0 + tx;
    g_wph[o] = h; g_wpl[o] = l;
  }
}

// ---------------- QK^T: 3-tile smem, 2 CTAs/SM ----------------
__device__ __forceinline__ void qk_epilogue(float* __restrict__ S, int ib, int jb,
                                            int wm, int wn, int lane, float acc[2][8][4]) {
#pragma unroll
  for (int mt = 0; mt < 2; mt++)
#pragma unroll
    for (int nt = 0; nt < 8; nt++)
#pragma unroll
      for (int e = 0; e < 4; e++) acc[mt][nt][e] *= 0.25f;
  int jc = jb * 2 + wn;
#pragma unroll
  for (int mt = 0; mt < 2; mt++) {
    int r0 = ib*128 + wm*32 + mt*16 + (lane >> 2);
    float mx0 = -3.4e38f, mx1 = -3.4e38f;
#pragma unroll
    for (int nt = 0; nt < 8; nt++) {
      mx0 = fmaxf(mx0, fmaxf(acc[mt][nt][0], acc[mt][nt][1]));
      mx1 = fmaxf(mx1, fmaxf(acc[mt][nt][2], acc[mt][nt][3]));
    }
    mx0 = fmaxf(mx0, __shfl_xor_sync(~0u, mx0, 1));
    mx0 = fmaxf(mx0, __shfl_xor_sync(~0u, mx0, 2));
    mx1 = fmaxf(mx1, __shfl_xor_sync(~0u, mx1, 1));
    mx1 = fmaxf(mx1, __shfl_xor_sync(~0u, mx1, 2));
    float s0 = 0.f, s1 = 0.f;
#pragma unroll
    for (int nt = 0; nt < 8; nt++) {
      s0 += __expf(acc[mt][nt][0] - mx0) + __expf(acc[mt][nt][1] - mx0);
      s1 += __expf(acc[mt][nt][2] - mx1) + __expf(acc[mt][nt][3] - mx1);
    }
    s0 += __shfl_xor_sync(~0u, s0, 1); s0 += __shfl_xor_sync(~0u, s0, 2);
    s1 += __shfl_xor_sync(~0u, s1, 1); s1 += __shfl_xor_sync(~0u, s1, 2);
    if ((lane & 3) == 0) {
      g_tmax[(size_t)jc*SEQ + r0] = mx0;     g_tsum[(size_t)jc*SEQ + r0] = s0;
      g_tmax[(size_t)jc*SEQ + r0 + 8] = mx1; g_tsum[(size_t)jc*SEQ + r0 + 8] = s1;
    }
    int colb = jb*128 + wn*64 + 2*(lane & 3);
#pragma unroll
    for (int nt = 0; nt < 8; nt++) {
      *(float2*)(S + (size_t)r0*SEQ + colb + nt*8)     = make_float2(acc[mt][nt][0], acc[mt][nt][1]);
      *(float2*)(S + (size_t)(r0+8)*SEQ + colb + nt*8) = make_float2(acc[mt][nt][2], acc[mt][nt][3]);
    }
  }
}

__global__ __launch_bounds__(256, 2) void k_qk_mma(float* __restrict__ S) {
  extern __shared__ char dsm[];
  uint32_t sb = smem_u32(dsm);
  int tid = threadIdx.x, lane = tid & 31, wid = tid >> 5;
  int wm = wid & 3, wn = wid >> 2;
  int ib = blockIdx.x, jb0 = blockIdx.y * 2;

  load_tile(sb + OAH, g_qh + (size_t)ib*128*NS, NS, tid);
  load_tile(sb + OAL, g_ql + (size_t)ib*128*NS, NS, tid);
  load_tile(sb + OB2, g_kh + (size_t)jb0*128*NS, NS, tid);
  CP_COMMIT();
  CP_WAIT0();
  __syncthreads();

#pragma unroll
  for (int j = 0; j < 2; j++) {
    int jb = jb0 + j;
    float acc[2][8][4] = {};
    // B buffer holds kh(jb)
    gemm_pass(sb + OAH, sb + OB2, lane, wm, wn, acc);
    gemm_pass(sb + OAL, sb + OB2, lane, wm, wn, acc);
    __syncthreads();
    load_tile(sb + OB2, g_kl + (size_t)jb*128*NS, NS, tid);
    CP_COMMIT(); CP_WAIT0();
    __syncthreads();
    gemm_pass(sb + OAH, sb + OB2, lane, wm, wn, acc);
    __syncthreads();
    if (j == 0) {
      load_tile(sb + OB2, g_kh + (size_t)(jb0+1)*128*NS, NS, tid);
      CP_COMMIT();
    }
    qk_epilogue(S, ib, jb, wm, wn, lane, acc);   // overlaps with next kh load
    if (j == 0) {
      CP_WAIT0();
      __syncthreads();
    }
  }
}

__global__ void k_combine() {
  int row = blockIdx.x * 256 + threadIdx.x;
  float mx = -3.4e38f;
  for (int j = 0; j < 128; j++) mx = fmaxf(mx, g_tmax[(size_t)j*SEQ + row]);
  float s = 0.f;
  for (int j = 0; j < 128; j++) s += g_tsum[(size_t)j*SEQ + row] * __expf(g_tmax[(size_t)j*SEQ + row] - mx);
  g_RM[row] = mx;
  g_RSI[row] = 1.0f / s;
}

// ---------------- softmax + attn write + attn@V: 3-tile smem, 2 CTAs/SM ----------------
__global__ __launch_bounds__(256, 2) void k_ctx_mma(float* __restrict__ S) {
  extern __shared__ char dsm[];
  uint32_t sb = smem_u32(dsm);
  int tid = threadIdx.x, lane = tid & 31, wid = tid >> 5;
  int wm = wid & 3, wn = wid >> 2;
  int ib = blockIdx.x, sp = blockIdx.y;

  int crow = tid >> 1;
  int cbase = (tid & 1) * 64;
  float m = g_RM[ib*128 + crow];
  float li = g_RSI[ib*128 + crow];

  float acc[2][8][4] = {};
  for (int c = 0; c < 8; c++) {
    int k0 = sp*1024 + c*128;
    load_tile(sb + OB2, g_vth + k0, SEQ, tid);
    CP_COMMIT();
    // convert S chunk c -> attn (global) + bf16 hi/lo A tiles (overlaps vth load)
    float2* srow = (float2*)(S + (size_t)(ib*128 + crow)*SEQ + k0 + cbase);
    uint32_t abase = sb + (uint32_t)((crow * TPAD + cbase) << 1);
#pragma unroll 8
    for (int i = 0; i < 32; i++) {
      float2 s2 = srow[i];
      float a0 = __expf(s2.x - m) * li;
      float a1 = __expf(s2.y - m) * li;
      srow[i] = make_float2(a0, a1);
      __nv_bfloat16 h0, l0, h1, l1;
      split16(a0, h0, l0); split16(a1, h1, l1);
      sts32(abase + OAH + i*4, packbf(h0, h1));
      sts32(abase + OAL + i*4, packbf(l0, l1));
    }
    CP_WAIT0();
    __syncthreads();
    gemm_pass(sb + OAH, sb + OB2, lane, wm, wn, acc);
    gemm_pass(sb + OAL, sb + OB2, lane, wm, wn, acc);
    __syncthreads();
    load_tile(sb + OB2, g_vtl + k0, SEQ, tid);
    CP_COMMIT(); CP_WAIT0();
    __syncthreads();
    gemm_pass(sb + OAH, sb + OB2, lane, wm, wn, acc);
    __syncthreads();
  }
#pragma unroll
  for (int mt = 0; mt < 2; mt++) {
    int r0 = ib*128 + wm*32 + mt*16 + (lane >> 2);
    int colb = wn*64 + 2*(lane & 3);
#pragma unroll
    for (int nt = 0; nt < 8; nt++) {
      *(float2*)(g_ctxp + ((size_t)sp*SEQ + r0)*NS + colb + nt*8)     = make_float2(acc[mt][nt][0], acc[mt][nt][1]);
      *(float2*)(g_ctxp + ((size_t)sp*SEQ + r0 + 8)*NS + colb + nt*8) = make_float2(acc[mt][nt][2], acc[mt][nt][3]);
    }
  }
}

__global__ void k_ctxred() {
  size_t idx = (size_t)blockIdx.x * 256 + threadIdx.x;
  float acc = 0.f;
#pragma unroll
  for (int s = 0; s < 8; s++) acc += g_ctxp[(size_t)s*SEQ*NS + idx];
  __nv_bfloat16 h, l;
  split16(acc, h, l);
  g_ch[idx] = h; g_clo[idx] = l;
}

// ---------------- out = ctx @ Wp + bp: 3-tile, 2 CTAs/SM ----------------
__global__ __launch_bounds__(256, 2) void k_out_mma(float* __restrict__ out, const float* __restrict__ bp) {
  extern __shared__ char dsm[];
  uint32_t sb = smem_u32(dsm);
  int tid = threadIdx.x, lane = tid & 31, wid = tid >> 5;
  int wm = wid & 3, wn = wid >> 2;
  int ib = blockIdx.x, cb = blockIdx.y;

  load_tile(sb + OAH, g_ch  + (size_t)ib*128*NS, NS, tid);
  load_tile(sb + OAL, g_clo + (size_t)ib*128*NS, NS, tid);
  load_tile(sb + OB2, g_wph + (size_t)cb*128*NS, NS, tid);
  CP_COMMIT(); CP_WAIT0();
  __syncthreads();

  float acc[2][8][4] = {};
  gemm_pass(sb + OAH, sb + OB2, lane, wm, wn, acc);
  gemm_pass(sb + OAL, sb + OB2, lane, wm, wn, acc);
  __syncthreads();
  load_tile(sb + OB2, g_wpl + (size_t)cb*128*NS, NS, tid);
  CP_COMMIT(); CP_WAIT0();
  __syncthreads();
  gemm_pass(sb + OAH, sb + OB2, lane, wm, wn, acc);

#pragma unroll
  for (int mt = 0; mt < 2; mt++) {
    int r0 = ib*128 + wm*32 + mt*16 + (lane >> 2);
#pragma unroll
    for (int nt = 0; nt < 8; nt++) {
      int gc = cb*128 + wn*64 + nt*8 + 2*(lane & 3);
      if (gc + 1 < OUTD) {
        out[(size_t)r0*OUTD + gc]         = acc[mt][nt][0] + bp[gc];
        out[(size_t)r0*OUTD + gc + 1]     = acc[mt][nt][1] + bp[gc + 1];
        out[(size_t)(r0+8)*OUTD + gc]     = acc[mt][nt][2] + bp[gc];
        out[(size_t)(r0+8)*OUTD + gc + 1] = acc[mt][nt][3] + bp[gc + 1];
      } else if (gc < OUTD) {
        out[(size_t)r0*OUTD + gc]     = acc[mt][nt][0] + bp[gc];
        out[(size_t)(r0+8)*OUTD + gc] = acc[mt][nt][2] + bp[gc];
      }
    }
  }
}

// ---------------- launch ----------------
extern "C" void kernel_launch(void* const* d_in, const int* in_sizes, int n_in,
                              void* d_out, int out_size) {
  const float* q  = (const float*)d_in[0];
  const float* kk = (const float*)d_in[1];
  const float* vv = (const float*)d_in[2];
  const float* GA = (const float*)d_in[3];
  const float* GB = (const float*)d_in[4];
  const float* Wp = (const float*)d_in[5];
  const float* bp = (const float*)d_in[6];
  float* out = (float*)d_out;

  cudaFuncSetAttribute(k_powers_f,    cudaFuncAttributeMaxDynamicSharedMemorySize, POW_SM);
  cudaFuncSetAttribute(k_localconv_h, cudaFuncAttributeMaxDynamicSharedMemorySize, SCAN2_SM);
  cudaFuncSetAttribute(k_boundary_h,  cudaFuncAttributeMaxDynamicSharedMemorySize, SCAN2_SM);
  cudaFuncSetAttribute(k_propagate_h, cudaFuncAttributeMaxDynamicSharedMemorySize, SCAN2_SM);
  cudaFuncSetAttribute(k_qk_mma,      cudaFuncAttributeMaxDynamicSharedMemorySize, GEMM3_SM);
  cudaFuncSetAttribute(k_ctx_mma,     cudaFuncAttributeMaxDynamicSharedMemorySize, GEMM3_SM);
  cudaFuncSetAttribute(k_out_mma,     cudaFuncAttributeMaxDynamicSharedMemorySize, GEMM3_SM);

  float* pFB;
  cudaGetSymbolAddress((void**)&pFB, g_attn_fb);
  float* S = (out_size >= (int)((size_t)SEQ*OUTD + (size_t)SEQ*SEQ)) ? out + (size_t)SEQ*OUTD : pFB;

  k_init<<<128, 128>>>(GA);
  k_prep_small<<<1, 256>>>(GB);
  k_powers_f<<<191, 256, POW_SM>>>(GB);
  k_localconv_h<<<dim3(64, 3), 256, SCAN2_SM>>>(q, kk, vv);
  k_zeroB<<<96, 256>>>();
  k_boundary_h<<<dim3(64, 2), 256, SCAN2_SM>>>();
  k_propagate_h<<<dim3(128, 2), 256, SCAN2_SM>>>();
  k_prep_qk<<<8192, 256>>>();
  k_prep_vt<<<dim3(256, 4), dim3(32, 8)>>>();
  k_prep_wpt<<<dim3(32, 4), dim3(32, 8)>>>(Wp);
  k_qk_mma<<<dim3(64, 32), 256, GEMM3_SM>>>(S);
  k_combine<<<32, 256>>>();
  k_ctx_mma<<<dim3(64, 8), 256, GEMM3_SM>>>(S);
  k_ctxred<<<4096, 256>>>();
  k_out_mma<<<dim3(64, 8), 256, GEMM3_SM>>>(out, bp);
}

// round 13
// speedup vs baseline: 1.0929x; 1.0929x over previous
#include <cuda_runtime.h>
#include <cuda_bf16.h>
#include <math.h>
#include <stdint.h>
typedef unsigned long long ull;

#define NS   128
#define SEQ  8192
#define OUTD 1000

// ---------------- device scratch ----------------
__device__ float g_PT[(size_t)2 * NS * NS];
__device__ float g_cs[(size_t)3 * SEQ * NS];
__device__ float g_U[3 * 64 * NS];
__device__ float g_B[3 * 64 * NS];
__device__ float g_ctxp[(size_t)8 * SEQ * NS];
__device__ float g_attn_fb[(size_t)SEQ * SEQ];
__device__ float g_tmax[(size_t)128 * SEQ];
__device__ float g_tsum[(size_t)128 * SEQ];
__device__ float g_RM[SEQ];
__device__ float g_RSI[SEQ];
__device__ __align__(256) __nv_bfloat16 g_qh[(size_t)SEQ * NS], g_ql[(size_t)SEQ * NS];
__device__ __align__(256) __nv_bfloat16 g_kh[(size_t)SEQ * NS], g_kl[(size_t)SEQ * NS];
__device__ __align__(256) __nv_bfloat16 g_vth[(size_t)NS * SEQ], g_vtl[(size_t)NS * SEQ];
__device__ __align__(256) __nv_bfloat16 g_ch[(size_t)SEQ * NS], g_clo[(size_t)SEQ * NS];
__device__ __align__(256) __nv_bfloat16 g_wph[(size_t)1024 * NS], g_wpl[(size_t)1024 * NS];
__device__ __align__(256) __nv_bfloat16 g_PTth[(size_t)129 * NS * NS], g_PTtl[(size_t)129 * NS * NS];
__device__ __align__(256) __nv_bfloat16 g_QTth[(size_t)64 * NS * NS],  g_QTtl[(size_t)64 * NS * NS];
__device__ __align__(256) __nv_bfloat16 g_Kth[NS * NS], g_Ktl[NS * NS];

// ---------------- PTX helpers ----------------
__device__ __forceinline__ uint32_t smem_u32(const void* p) {
  uint32_t a;
  asm("{ .reg .u64 t; cvta.to.shared.u64 t, %1; cvt.u32.u64 %0, t; }" : "=r"(a) : "l"(p));
  return a;
}
__device__ __forceinline__ void cp16(uint32_t d, const void* s) {
  asm volatile("cp.async.cg.shared.global [%0], [%1], 16;" ::"r"(d),"l"(s):"memory");
}
#define CP_COMMIT() asm volatile("cp.async.commit_group;" :::"memory")
#define CP_WAIT0()  asm volatile("cp.async.wait_group 0;" :::"memory")
#define CP_WAIT1()  asm volatile("cp.async.wait_group 1;" :::"memory")
__device__ __forceinline__ void sts32(uint32_t a, uint32_t v) {
  asm volatile("st.shared.b32 [%0], %1;" ::"r"(a),"r"(v):"memory");
}
__device__ __forceinline__ void ldm4(uint32_t a, uint32_t f[4]) {
  asm volatile("ldmatrix.sync.aligned.m8n8.x4.shared.b16 {%0,%1,%2,%3}, [%4];"
    : "=r"(f[0]),"=r"(f[1]),"=r"(f[2]),"=r"(f[3]) : "r"(a));
}
__device__ __forceinline__ void mma16816(float c[4], const uint32_t a[4], const uint32_t b0, const uint32_t b1) {
  asm volatile("mma.sync.aligned.m16n8k16.row.col.f32.bf16.bf16.f32 "
    "{%0,%1,%2,%3},{%4,%5,%6,%7},{%8,%9},{%0,%1,%2,%3};"
    : "+f"(c[0]),"+f"(c[1]),"+f"(c[2]),"+f"(c[3])
    : "r"(a[0]),"r"(a[1]),"r"(a[2]),"r"(a[3]),"r"(b0),"r"(b1));
}

// padded bf16 tile: 128 rows x 136 cols
#define TPAD 136
#define TILE_B (128 * TPAD * 2)
#define OAH 0u
#define OAL (1u * TILE_B)
#define OBH (2u * TILE_B)
#define OBL (3u * TILE_B)
#define OB1H (4u * TILE_B)
#define OB1L (5u * TILE_B)
#define GEMM2_SM (6 * TILE_B)
#define GEMM_SM  (4 * TILE_B)
#define SCAN2_SM (4 * TILE_B + 512)
#define POW_SM   (2 * 128 * 132 * 4)

// 256-thread tile loader
__device__ __forceinline__ void load_tile(uint32_t sbt, const __nv_bfloat16* src, int stride, int tid) {
#pragma unroll
  for (int t = tid; t < 2048; t += 256) {
    int row = t >> 4, col = (t & 15) << 3;
    cp16(sbt + row * (TPAD * 2) + (col << 1), src + (size_t)row * stride + col);
  }
}

// 8-warp gemm pass: warp = 32m x 64n — SOFTWARE-PIPELINED (frag double buffer).
// Loads for ks+1 are issued (in program order) before the mmas of ks, so the
// ldmatrix latency overlaps mma execution even with asm volatile ordering.
__device__ __forceinline__ void gemm_pass(uint32_t sA, uint32_t sB, int lane, int wm, int wn,
                                          float acc[2][8][4]) {
  uint32_t aB0 = sA + (uint32_t)(((wm*32 + (lane & 15)) * TPAD + ((lane >> 4) << 3)) << 1);
  uint32_t aB1 = aB0 + (uint32_t)((16 * TPAD) << 1);
  uint32_t bB[4];
#pragma unroll
  for (int np = 0; np < 4; np++)
    bB[np] = sB + (uint32_t)(((wn*64 + np*16 + (lane & 7) + ((lane >> 4) << 3)) * TPAD + (lane & 8)) << 1);

  uint32_t afr[2][2][4];
  uint32_t bfr[2][4][4];
  ldm4(aB0, afr[0][0]);
  ldm4(aB1, afr[0][1]);
#pragma unroll
  for (int np = 0; np < 4; np++) ldm4(bB[np], bfr[0][np]);

#pragma unroll
  for (int ks = 0; ks < 8; ks++) {
    int cur = ks & 1, nxt = cur ^ 1;
    if (ks < 7) {
      uint32_t off = (uint32_t)((ks + 1) * 32);   // 16 bf16 cols = 32 bytes
      ldm4(aB0 + off, afr[nxt][0]);
      ldm4(aB1 + off, afr[nxt][1]);
#pragma unroll
      for (int np = 0; np < 4; np++) ldm4(bB[np] + off, bfr[nxt][np]);
    }
#pragma unroll
    for (int np = 0; np < 4; np++) {
#pragma unroll
      for (int mt = 0; mt < 2; mt++) {
        mma16816(acc[mt][np * 2],     afr[cur][mt], bfr[cur][np][0], bfr[cur][np][1]);
        mma16816(acc[mt][np * 2 + 1], afr[cur][mt], bfr[cur][np][2], bfr[cur][np][3]);
      }
    }
  }
}
__device__ __forceinline__ void gemm3v(uint32_t aH, uint32_t aL, uint32_t bH, uint32_t bL,
                                       int lane, int wm, int wn, float acc[2][8][4]) {
  gemm_pass(aH, bH, lane, wm, wn, acc);
  gemm_pass(aH, bL, lane, wm, wn, acc);
  gemm_pass(aL, bH, lane, wm, wn, acc);
}

__device__ __forceinline__ void split16(float x, __nv_bfloat16& h, __nv_bfloat16& l) {
  h = __float2bfloat16(x);
  l = __float2bfloat16(x - __bfloat162float(h));
}
__device__ __forceinline__ uint32_t packbf(__nv_bfloat16 lo_e, __nv_bfloat16 hi_e) {
  return ((uint32_t)__bfloat16_as_ushort(hi_e) << 16) | __bfloat16_as_ushort(lo_e);
}
__device__ __forceinline__ void split_store2(uint32_t sb, uint32_t offH, uint32_t offL,
                                             int r, int c0, float x0, float x1) {
  __nv_bfloat16 h0, l0, h1, l1;
  split16(x0, h0, l0); split16(x1, h1, l1);
  uint32_t off = (uint32_t)(r * TPAD + c0) << 1;
  sts32(sb + offH + off, packbf(h0, h1));
  sts32(sb + offL + off, packbf(l0, l1));
}

// ---------------- f32x2 mm (k_powers only — accuracy anchor) ----------------
__device__ __forceinline__ void mm128(const float* As, const float* Bs, int tx, int ty, ull acc[8][4]) {
#pragma unroll 4
  for (int kk = 0; kk < 128; kk++) {
    ull bp[4];
#pragma unroll
    for (int j = 0; j < 4; j++) bp[j] = *(const ull*)&Bs[kk*132 + tx*8 + j*2];
#pragma unroll
    for (int i = 0; i < 8; i++) {
      float a = As[(ty*8+i)*132 + kk];
      ull ap; asm("mov.b64 %0,{%1,%1};" : "=l"(ap) : "f"(a));
#pragma unroll
      for (int j = 0; j < 4; j++)
        asm("fma.rn.f32x2 %0,%1,%2,%0;" : "+l"(acc[i][j]) : "l"(ap), "l"(bp[j]));
    }
  }
}
__device__ __forceinline__ float2 upk(ull p) {
  float2 r; asm("mov.b64 {%0,%1}, %2;" : "=f"(r.x), "=f"(r.y) : "l"(p)); return r;
}

__global__ void k_init(const float* __restrict__ GA) {
  int m = blockIdx.x, n = threadIdx.x;
  g_PT[m*NS+n] = (m==n) ? 1.f : 0.f;
  g_PT[NS*NS + m*NS + n] = GA[n*NS + m];
}

__global__ void k_prep_small(const float* __restrict__ GB) {
  int tid = threadIdx.x;
  __nv_bfloat16 one = __float2bfloat16(1.f), zero = __float2bfloat16(0.f);
  for (int l = tid; l < 8192; l += 256) {
    int n = l >> 6, k0 = (l & 63) * 2;
    uint32_t h = 0;
    if (n == k0) h = packbf(one, zero);
    else if (n == k0 + 1) h = packbf(zero, one);
    *(uint32_t*)(g_QTth + n*128 + k0) = h;
    *(uint32_t*)(g_QTtl + n*128 + k0) = 0;
  }
  if (tid < 128) {
    __nv_bfloat16 h, l;
    split16(GB[tid], h, l);
    g_Kth[tid*128 + 0] = h;
    g_Ktl[tid*128 + 0] = l;
  }
}

__global__ __launch_bounds__(256) void k_powers_f(const float* __restrict__ GB) {
  extern __shared__ float sm[];
  float* R = sm;
  float* G = sm + 128*132;
  int b = blockIdx.x, tid = threadIdx.x, tx = tid & 15, ty = tid >> 4;
  int e; __nv_bfloat16 *dh, *dl;
  if (b < 128) { e = b + 1; dh = g_PTth + (size_t)(b+1)*NS*NS; dl = g_PTtl + (size_t)(b+1)*NS*NS; }
  else { int p = b - 127; e = p << 7; dh = g_QTth + (size_t)p*NS*NS; dl = g_QTtl + (size_t)p*NS*NS; }
  const float* GAT = g_PT + NS*NS;
  for (int l = tid; l < NS*NS; l += 256) {
    int r = l >> 7, c = l & 127;
    float v = GAT[l];
    G[r*132+c] = v; R[r*132+c] = v;
  }
  __syncthreads();
  int msb = 31 - __clz(e);
  for (int bit = msb - 1; bit >= 0; bit--) {
    {
      ull acc[8][4] = {};
      mm128(R, R, tx, ty, acc);
      __syncthreads();
#pragma unroll
      for (int i = 0; i < 8; i++)
#pragma unroll
        for (int j = 0; j < 4; j++) {
          float2 v = upk(acc[i][j]);
          R[(ty*8+i)*132 + tx*8 + j*2] = v.x;
          R[(ty*8+i)*132 + tx*8 + j*2 + 1] = v.y;
        }
      __syncthreads();
    }
    if ((e >> bit) & 1) {
      ull acc[8][4] = {};
      mm128(R, G, tx, ty, acc);
      __syncthreads();
#pragma unroll
      for (int i = 0; i < 8; i++)
#pragma unroll
        for (int j = 0; j < 4; j++) {
          float2 v = upk(acc[i][j]);
          R[(ty*8+i)*132 + tx*8 + j*2] = v.x;
          R[(ty*8+i)*132 + tx*8 + j*2 + 1] = v.y;
        }
      __syncthreads();
    }
  }
  for (int l = tid; l < 8192; l += 256) {
    int n = l >> 6, k0 = (l & 63) * 2;
    __nv_bfloat16 h0, l0, h1, l1;
    split16(R[k0*132 + n], h0, l0);
    split16(R[(k0+1)*132 + n], h1, l1);
    *(uint32_t*)(dh + (size_t)n*128 + k0) = packbf(h0, h1);
    *(uint32_t*)(dl + (size_t)n*128 + k0) = packbf(l0, l1);
  }
  if (b < 127 && tid < 128) {
    int n = tid;
    float acc = 0.f;
#pragma unroll 4
    for (int m = 0; m < 128; m++) acc = fmaf(R[m*132 + n], GB[m], acc);
    __nv_bfloat16 h, l;
    split16(acc, h, l);
    g_Kth[n*128 + (b+1)] = h;
    g_Ktl[n*128 + (b+1)] = l;
  }
}

// ---------------- scan GEMMs ----------------
__global__ __launch_bounds__(256) void k_localconv_h(const float* __restrict__ fq,
                                                     const float* __restrict__ fk,
                                                     const float* __restrict__ fv) {
  extern __shared__ char dsm[];
  uint32_t sb = smem_u32(dsm);
  float* fs = (float*)(dsm + 4*TILE_B);
  int ci = blockIdx.x, ch = blockIdx.y;
  const float* f = (ch == 0) ? fq : ((ch == 1) ? fk : fv);
  int tid = threadIdx.x, lane = tid & 31, wid = tid >> 5;
  int wm = wid & 3, wn = wid >> 2;
  load_tile(sb + OBH, g_Kth, 128, tid);
  load_tile(sb + OBL, g_Ktl, 128, tid);
  CP_COMMIT();
  if (tid < 128) fs[tid] = f[ci*128 + tid];
  __syncthreads();
  for (int l = tid; l < 8192; l += 256) {
    int r = l >> 6, c0 = (l & 63) * 2;
    float x0 = (c0 <= r) ? fs[r - c0] : 0.f;
    float x1 = (c0 + 1 <= r) ? fs[r - c0 - 1] : 0.f;
    split_store2(sb, OAH, OAL, r, c0, x0, x1);
  }
  CP_WAIT0();
  __syncthreads();
  float acc[2][8][4] = {};
  gemm3v(sb + OAH, sb + OAL, sb + OBH, sb + OBL, lane, wm, wn, acc);
  float* Cc = g_cs + ((size_t)ch*SEQ + (size_t)ci*128) * NS;
#pragma unroll
  for (int mt = 0; mt < 2; mt++) {
    int r0 = wm*32 + mt*16 + (lane >> 2);
#pragma unroll
    for (int nt = 0; nt < 8; nt++) {
      int gc = wn*64 + nt*8 + 2*(lane & 3);
      *(float2*)(Cc + (size_t)r0*NS + gc)     = make_float2(acc[mt][nt][0], acc[mt][nt][1]);
      *(float2*)(Cc + (size_t)(r0+8)*NS + gc) = make_float2(acc[mt][nt][2], acc[mt][nt][3]);
      if (r0 + 8 == 127)
        *(float2*)(g_U + (size_t)(ch*64 + ci)*NS + gc) = make_float2(acc[mt][nt][2], acc[mt][nt][3]);
    }
  }
}

__global__ void k_zeroB() {
  int i = blockIdx.x * 256 + threadIdx.x;
  if (i < 3*64*NS) g_B[i] = 0.f;
}

__global__ __launch_bounds__(256) void k_boundary_h() {
  extern __shared__ char dsm[];
  uint32_t sb = smem_u32(dsm);
  int p = blockIdx.x, rb = blockIdx.y;
  int tid = threadIdx.x, lane = tid & 31, wid = tid >> 5;
  int wm = wid & 3, wn = wid >> 2;
  load_tile(sb + OBH, g_QTth + (size_t)p*NS*NS, 128, tid);
  load_tile(sb + OBL, g_QTtl + (size_t)p*NS*NS, 128, tid);
  CP_COMMIT();
  for (int l = tid; l < 8192; l += 256) {
    int r = l >> 6, c0 = (l & 63) * 2;
    int gr = rb*128 + r;
    bool ok = (gr < 192) && ((gr & 63) >= p);
    float x0 = ok ? g_U[(size_t)(gr - p)*NS + c0] : 0.f;
    float x1 = ok ? g_U[(size_t)(gr - p)*NS + c0 + 1] : 0.f;
    split_store2(sb, OAH, OAL, r, c0, x0, x1);
  }
  CP_WAIT0();
  __syncthreads();
  float acc[2][8][4] = {};
  gemm3v(sb + OAH, sb + OAL, sb + OBH, sb + OBL, lane, wm, wn, acc);
#pragma unroll
  for (int mt = 0; mt < 2; mt++) {
    int r0 = wm*32 + mt*16 + (lane >> 2);
#pragma unroll
    for (int e2 = 0; e2 < 2; e2++) {
      int gr = rb*128 + r0 + e2*8;
      if (gr < 192 && (gr & 63) >= p) {
#pragma unroll
        for (int nt = 0; nt < 8; nt++) {
          int gc = wn*64 + nt*8 + 2*(lane & 3);
          atomicAdd(&g_B[(size_t)gr*NS + gc],     acc[mt][nt][e2*2]);
          atomicAdd(&g_B[(size_t)gr*NS + gc + 1], acc[mt][nt][e2*2 + 1]);
        }
      }
    }
  }
}

__global__ __launch_bounds__(256) void k_propagate_h() {
  extern __shared__ char dsm[];
  uint32_t sb = smem_u32(dsm);
  int r = blockIdx.x, rb = blockIdx.y;
  int tid = threadIdx.x, lane = tid & 31, wid = tid >> 5;
  int wm = wid & 3, wn = wid >> 2;
  load_tile(sb + OBH, g_PTth + (size_t)(r+1)*NS*NS, 128, tid);
  load_tile(sb + OBL, g_PTtl + (size_t)(r+1)*NS*NS, 128, tid);
  CP_COMMIT();
  for (int l = tid; l < 8192; l += 256) {
    int rr = l >> 6, c0 = (l & 63) * 2;
    int gr = rb*128 + rr;
    float x0 = (gr < 192) ? g_B[(size_t)gr*NS + c0] : 0.f;
    float x1 = (gr < 192) ? g_B[(size_t)gr*NS + c0 + 1] : 0.f;
    split_store2(sb, OAH, OAL, rr, c0, x0, x1);
  }
  CP_WAIT0();
  __syncthreads();
  float acc[2][8][4] = {};
  gemm3v(sb + OAH, sb + OAL, sb + OBH, sb + OBL, lane, wm, wn, acc);
#pragma unroll
  for (int mt = 0; mt < 2; mt++) {
    int r0 = wm*32 + mt*16 + (lane >> 2);
#pragma unroll
    for (int e2 = 0; e2 < 2; e2++) {
      int gr = rb*128 + r0 + e2*8;
      if (gr < 192 && (gr & 63) < 63) {
        int ch = gr >> 6, ic = (gr & 63) + 1;
        float* dst = &g_cs[((size_t)ch*SEQ + (size_t)ic*128 + r) * NS];
#pragma unroll
        for (int nt = 0; nt < 8; nt++) {
          int gc = wn*64 + nt*8 + 2*(lane & 3);
          dst[gc]     += acc[mt][nt][e2*2];
          dst[gc + 1] += acc[mt][nt][e2*2 + 1];
        }
      }
    }
  }
}

// ---------------- bf16 hi/lo preps ----------------
__global__ void k_prep_qk() {
  size_t idx = (size_t)blockIdx.x * 256 + threadIdx.x;
  float x = g_cs[idx];
  __nv_bfloat16 h, l;
  split16(x, h, l);
  size_t SN = (size_t)SEQ * NS;
  if (idx < SN) { g_qh[idx] = h; g_ql[idx] = l; }
  else          { g_kh[idx - SN] = h; g_kl[idx - SN] = l; }
}
__global__ void k_prep_vt() {
  __shared__ float t[32][33];
  int t0 = blockIdx.x * 32, n0 = blockIdx.y * 32;
  int tx = threadIdx.x, ty = threadIdx.y;
  const float* v = g_cs + (size_t)2 * SEQ * NS;
#pragma unroll
  for (int j = 0; j < 32; j += 8) t[ty+j][tx] = v[(size_t)(t0 + ty + j)*NS + n0 + tx];
  __syncthreads();
#pragma unroll
  for (int j = 0; j < 32; j += 8) {
    __nv_bfloat16 h, l;
    split16(t[tx][ty+j], h, l);
    size_t o = (size_t)(n0 + ty + j) * SEQ + t0 + tx;
    g_vth[o] = h; g_vtl[o] = l;
  }
}
__global__ void k_prep_wpt(const float* __restrict__ Wp) {
  __shared__ float t[32][33];
  int n0 = blockIdx.x * 32, k0 = blockIdx.y * 32;
  int tx = threadIdx.x, ty = threadIdx.y;
#pragma unroll
  for (int j = 0; j < 32; j += 8) {
    int n = n0 + tx;
    t[ty+j][tx] = (n < OUTD) ? Wp[(size_t)(k0 + ty + j)*OUTD + n] : 0.f;
  }
  __syncthreads();
#pragma unroll
  for (int j = 0; j < 32; j += 8) {
    __nv_bfloat16 h, l;
    split16(t[tx][ty+j], h, l);
    size_t o = (size_t)(n0 + ty + j) * NS + k0 + tx;
    g_wph[o] = h; g_wpl[o] = l;
  }
}

// ---------------- QK^T (2 K-tiles/CTA, double-buffered B) + fused stats ----------------
__device__ __forceinline__ void qk_epilogue(float* __restrict__ S, int ib, int jb,
                                            int wm, int wn, int lane, float acc[2][8][4]) {
#pragma unroll
  for (int mt = 0; mt < 2; mt++)
#pragma unroll
    for (int nt = 0; nt < 8; nt++)
#pragma unroll
      for (int e = 0; e < 4; e++) acc[mt][nt][e] *= 0.25f;
  int jc = jb * 2 + wn;
#pragma unroll
  for (int mt = 0; mt < 2; mt++) {
    int r0 = ib*128 + wm*32 + mt*16 + (lane >> 2);
    float mx0 = -3.4e38f, mx1 = -3.4e38f;
#pragma unroll
    for (int nt = 0; nt < 8; nt++) {
      mx0 = fmaxf(mx0, fmaxf(acc[mt][nt][0], acc[mt][nt][1]));
      mx1 = fmaxf(mx1, fmaxf(acc[mt][nt][2], acc[mt][nt][3]));
    }
    mx0 = fmaxf(mx0, __shfl_xor_sync(~0u, mx0, 1));
    mx0 = fmaxf(mx0, __shfl_xor_sync(~0u, mx0, 2));
    mx1 = fmaxf(mx1, __shfl_xor_sync(~0u, mx1, 1));
    mx1 = fmaxf(mx1, __shfl_xor_sync(~0u, mx1, 2));
    float s0 = 0.f, s1 = 0.f;
#pragma unroll
    for (int nt = 0; nt < 8; nt++) {
      s0 += __expf(acc[mt][nt][0] - mx0) + __expf(acc[mt][nt][1] - mx0);
      s1 += __expf(acc[mt][nt][2] - mx1) + __expf(acc[mt][nt][3] - mx1);
    }
    s0 += __shfl_xor_sync(~0u, s0, 1); s0 += __shfl_xor_sync(~0u, s0, 2);
    s1 += __shfl_xor_sync(~0u, s1, 1); s1 += __shfl_xor_sync(~0u, s1, 2);
    if ((lane & 3) == 0) {
      g_tmax[(size_t)jc*SEQ + r0] = mx0;     g_tsum[(size_t)jc*SEQ + r0] = s0;
      g_tmax[(size_t)jc*SEQ + r0 + 8] = mx1; g_tsum[(size_t)jc*SEQ + r0 + 8] = s1;
    }
    int colb = jb*128 + wn*64 + 2*(lane & 3);
#pragma unroll
    for (int nt = 0; nt < 8; nt++) {
      *(float2*)(S + (size_t)r0*SEQ + colb + nt*8)     = make_float2(acc[mt][nt][0], acc[mt][nt][1]);
      *(float2*)(S + (size_t)(r0+8)*SEQ + colb + nt*8) = make_float2(acc[mt][nt][2], acc[mt][nt][3]);
    }
  }
}

__global__ __launch_bounds__(256) void k_qk_mma(float* __restrict__ S) {
  extern __shared__ char dsm[];
  uint32_t sb = smem_u32(dsm);
  int tid = threadIdx.x, lane = tid & 31, wid = tid >> 5;
  int wm = wid & 3, wn = wid >> 2;
  int ib = blockIdx.x, jb0 = blockIdx.y * 2, jb1 = jb0 + 1;

  load_tile(sb + OAH, g_qh + (size_t)ib*128*NS, NS, tid);
  load_tile(sb + OAL, g_ql + (size_t)ib*128*NS, NS, tid);
  load_tile(sb + OBH, g_kh + (size_t)jb0*128*NS, NS, tid);
  load_tile(sb + OBL, g_kl + (size_t)jb0*128*NS, NS, tid);
  CP_COMMIT();
  load_tile(sb + OB1H, g_kh + (size_t)jb1*128*NS, NS, tid);
  load_tile(sb + OB1L, g_kl + (size_t)jb1*128*NS, NS, tid);
  CP_COMMIT();
  CP_WAIT1();
  __syncthreads();
  {
    float acc[2][8][4] = {};
    gemm3v(sb + OAH, sb + OAL, sb + OBH, sb + OBL, lane, wm, wn, acc);
    qk_epilogue(S, ib, jb0, wm, wn, lane, acc);
  }
  CP_WAIT0();
  __syncthreads();
  {
    float acc[2][8][4] = {};
    gemm3v(sb + OAH, sb + OAL, sb + OB1H, sb + OB1L, lane, wm, wn, acc);
    qk_epilogue(S, ib, jb1, wm, wn, lane, acc);
  }
}

__global__ void k_combine() {
  int row = blockIdx.x * 256 + threadIdx.x;
  float mx = -3.4e38f;
  for (int j = 0; j < 128; j++) mx = fmaxf(mx, g_tmax[(size_t)j*SEQ + row]);
  float s = 0.f;
  for (int j = 0; j < 128; j++) s += g_tsum[(size_t)j*SEQ + row] * __expf(g_tmax[(size_t)j*SEQ + row] - mx);
  g_RM[row] = mx;
  g_RSI[row] = 1.0f / s;
}

// ---------------- softmax + attn write + attn@V (double-buffered V) ----------------
__global__ __launch_bounds__(256) void k_ctx_mma(float* __restrict__ S) {
  extern __shared__ char dsm[];
  uint32_t sb = smem_u32(dsm);
  int tid = threadIdx.x, lane = tid & 31, wid = tid >> 5;
  int wm = wid & 3, wn = wid >> 2;
  int ib = blockIdx.x, sp = blockIdx.y;

  int crow = tid >> 1;
  int cbase = (tid & 1) * 64;
  float m = g_RM[ib*128 + crow];
  float li = g_RSI[ib*128 + crow];

  load_tile(sb + OBH, g_vth + sp*1024, SEQ, tid);
  load_tile(sb + OBL, g_vtl + sp*1024, SEQ, tid);
  CP_COMMIT();

  float acc[2][8][4] = {};
  for (int c = 0; c < 8; c++) {
    uint32_t bH = (c & 1) ? OB1H : OBH;
    uint32_t bL = (c & 1) ? OB1L : OBL;
    if (c < 7) {
      uint32_t nH = (c & 1) ? OBH : OB1H;
      uint32_t nL = (c & 1) ? OBL : OB1L;
      int kn = sp*1024 + (c+1)*128;
      load_tile(sb + nH, g_vth + kn, SEQ, tid);
      load_tile(sb + nL, g_vtl + kn, SEQ, tid);
      CP_COMMIT();
    }
    int k0 = sp*1024 + c*128;
    float2* srow = (float2*)(S + (size_t)(ib*128 + crow)*SEQ + k0 + cbase);
    uint32_t abase = sb + (uint32_t)((crow * TPAD + cbase) << 1);
#pragma unroll 8
    for (int i = 0; i < 32; i++) {
      float2 s2 = srow[i];
      float a0 = __expf(s2.x - m) * li;
      float a1 = __expf(s2.y - m) * li;
      srow[i] = make_float2(a0, a1);
      __nv_bfloat16 h0, l0, h1, l1;
      split16(a0, h0, l0); split16(a1, h1, l1);
      sts32(abase + OAH + i*4, packbf(h0, h1));
      sts32(abase + OAL + i*4, packbf(l0, l1));
    }
    if (c < 7) CP_WAIT1(); else CP_WAIT0();
    __syncthreads();
    gemm3v(sb + OAH, sb + OAL, sb + bH, sb + bL, lane, wm, wn, acc);
    __syncthreads();
  }
#pragma unroll
  for (int mt = 0; mt < 2; mt++) {
    int r0 = ib*128 + wm*32 + mt*16 + (lane >> 2);
    int colb = wn*64 + 2*(lane & 3);
#pragma unroll
    for (int nt = 0; nt < 8; nt++) {
      *(float2*)(g_ctxp + ((size_t)sp*SEQ + r0)*NS + colb + nt*8)     = make_float2(acc[mt][nt][0], acc[mt][nt][1]);
      *(float2*)(g_ctxp + ((size_t)sp*SEQ + r0 + 8)*NS + colb + nt*8) = make_float2(acc[mt][nt][2], acc[mt][nt][3]);
    }
  }
}

__global__ void k_ctxred() {
  size_t idx = (size_t)blockIdx.x * 256 + threadIdx.x;
  float acc = 0.f;
#pragma unroll
  for (int s = 0; s < 8; s++) acc += g_ctxp[(size_t)s*SEQ*NS + idx];
  __nv_bfloat16 h, l;
  split16(acc, h, l);
  g_ch[idx] = h; g_clo[idx] = l;
}

// ---------------- out = ctx @ Wp + bp ----------------
__global__ __launch_bounds__(256) void k_out_mma(float* __restrict__ out, const float* __restrict__ bp) {
  extern __shared__ char dsm[];
  uint32_t sb = smem_u32(dsm);
  int tid = threadIdx.x, lane = tid & 31, wid = tid >> 5;
  int wm = wid & 3, wn = wid >> 2;
  int ib = blockIdx.x, cb = blockIdx.y;

  load_tile(sb + OAH, g_ch  + (size_t)ib*128*NS, NS, tid);
  load_tile(sb + OAL, g_clo + (size_t)ib*128*NS, NS, tid);
  load_tile(sb + OBH, g_wph + (size_t)cb*128*NS, NS, tid);
  load_tile(sb + OBL, g_wpl + (size_t)cb*128*NS, NS, tid);
  CP_COMMIT(); CP_WAIT0();
  __syncthreads();

  float acc[2][8][4] = {};
  gemm3v(sb + OAH, sb + OAL, sb + OBH, sb + OBL, lane, wm, wn, acc);

#pragma unroll
  for (int mt = 0; mt < 2; mt++) {
    int r0 = ib*128 + wm*32 + mt*16 + (lane >> 2);
#pragma unroll
    for (int nt = 0; nt < 8; nt++) {
      int gc = cb*128 + wn*64 + nt*8 + 2*(lane & 3);
      if (gc + 1 < OUTD) {
        out[(size_t)r0*OUTD + gc]         = acc[mt][nt][0] + bp[gc];
        out[(size_t)r0*OUTD + gc + 1]     = acc[mt][nt][1] + bp[gc + 1];
        out[(size_t)(r0+8)*OUTD + gc]     = acc[mt][nt][2] + bp[gc];
        out[(size_t)(r0+8)*OUTD + gc + 1] = acc[mt][nt][3] + bp[gc + 1];
      } else if (gc < OUTD) {
        out[(size_t)r0*OUTD + gc]     = acc[mt][nt][0] + bp[gc];
        out[(size_t)(r0+8)*OUTD + gc] = acc[mt][nt][2] + bp[gc];
      }
    }
  }
}

// ---------------- launch ----------------
extern "C" void kernel_launch(void* const* d_in, const int* in_sizes, int n_in,
                              void* d_out, int out_size) {
  const float* q  = (const float*)d_in[0];
  const float* kk = (const float*)d_in[1];
  const float* vv = (const float*)d_in[2];
  const float* GA = (const float*)d_in[3];
  const float* GB = (const float*)d_in[4];
  const float* Wp = (const float*)d_in[5];
  const float* bp = (const float*)d_in[6];
  float* out = (float*)d_out;

  cudaFuncSetAttribute(k_powers_f,    cudaFuncAttributeMaxDynamicSharedMemorySize, POW_SM);
  cudaFuncSetAttribute(k_localconv_h, cudaFuncAttributeMaxDynamicSharedMemorySize, SCAN2_SM);
  cudaFuncSetAttribute(k_boundary_h,  cudaFuncAttributeMaxDynamicSharedMemorySize, SCAN2_SM);
  cudaFuncSetAttribute(k_propagate_h, cudaFuncAttributeMaxDynamicSharedMemorySize, SCAN2_SM);
  cudaFuncSetAttribute(k_qk_mma,      cudaFuncAttributeMaxDynamicSharedMemorySize, GEMM2_SM);
  cudaFuncSetAttribute(k_ctx_mma,     cudaFuncAttributeMaxDynamicSharedMemorySize, GEMM2_SM);
  cudaFuncSetAttribute(k_out_mma,     cudaFuncAttributeMaxDynamicSharedMemorySize, GEMM_SM);

  float* pFB;
  cudaGetSymbolAddress((void**)&pFB, g_attn_fb);
  float* S = (out_size >= (int)((size_t)SEQ*OUTD + (size_t)SEQ*SEQ)) ? out + (size_t)SEQ*OUTD : pFB;

  k_init<<<128, 128>>>(GA);
  k_prep_small<<<1, 256>>>(GB);
  k_powers_f<<<191, 256, POW_SM>>>(GB);
  k_localconv_h<<<dim3(64, 3), 256, SCAN2_SM>>>(q, kk, vv);
  k_zeroB<<<96, 256>>>();
  k_boundary_h<<<dim3(64, 2), 256, SCAN2_SM>>>();
  k_propagate_h<<<dim3(128, 2), 256, SCAN2_SM>>>();
  k_prep_qk<<<8192, 256>>>();
  k_prep_vt<<<dim3(256, 4), dim3(32, 8)>>>();
  k_prep_wpt<<<dim3(32, 4), dim3(32, 8)>>>(Wp);
  k_qk_mma<<<dim3(64, 32), 256, GEMM2_SM>>>(S);
  k_combine<<<32, 256>>>();
  k_ctx_mma<<<dim3(64, 8), 256, GEMM2_SM>>>(S);
  k_ctxred<<<4096, 256>>>();
  k_out_mma<<<dim3(64, 8), 256, GEMM_SM>>>(out, bp);
}

// round 14
// speedup vs baseline: 1.1442x; 1.0469x over previous
#include <cuda_runtime.h>
#include <cuda_bf16.h>
#include <cuda_fp16.h>
#include <math.h>
#include <stdint.h>
typedef unsigned long long ull;

#define NS   128
#define SEQ  8192
#define OUTD 1000

// ---------------- device scratch ----------------
__device__ float g_PT[(size_t)2 * NS * NS];
__device__ float g_cs[(size_t)3 * SEQ * NS];
__device__ float g_U[3 * 64 * NS];
__device__ float g_B[3 * 64 * NS];
__device__ float g_ctxp[(size_t)8 * SEQ * NS];
__device__ float g_attn_fb[(size_t)SEQ * SEQ];
__device__ float g_tmax[(size_t)128 * SEQ];
__device__ float g_tsum[(size_t)128 * SEQ];
__device__ float g_RM[SEQ];
__device__ float g_RSI[SEQ];
// fp16 q (hi only) and k (hi/lo) for 2-pass qk
__device__ __align__(256) __half g_qh[(size_t)SEQ * NS];
__device__ __align__(256) __half g_kh[(size_t)SEQ * NS], g_kl[(size_t)SEQ * NS];
// bf16 for ctx/out (3-pass)
__device__ __align__(256) __nv_bfloat16 g_vth[(size_t)NS * SEQ], g_vtl[(size_t)NS * SEQ];
__device__ __align__(256) __nv_bfloat16 g_ch[(size_t)SEQ * NS], g_clo[(size_t)SEQ * NS];
__device__ __align__(256) __nv_bfloat16 g_wph[(size_t)1024 * NS], g_wpl[(size_t)1024 * NS];
__device__ __align__(256) __nv_bfloat16 g_PTth[(size_t)129 * NS * NS], g_PTtl[(size_t)129 * NS * NS];
__device__ __align__(256) __nv_bfloat16 g_QTth[(size_t)64 * NS * NS],  g_QTtl[(size_t)64 * NS * NS];
__device__ __align__(256) __nv_bfloat16 g_Kth[NS * NS], g_Ktl[NS * NS];

// ---------------- PTX helpers ----------------
__device__ __forceinline__ uint32_t smem_u32(const void* p) {
  uint32_t a;
  asm("{ .reg .u64 t; cvta.to.shared.u64 t, %1; cvt.u32.u64 %0, t; }" : "=r"(a) : "l"(p));
  return a;
}
__device__ __forceinline__ void cp16(uint32_t d, const void* s) {
  asm volatile("cp.async.cg.shared.global [%0], [%1], 16;" ::"r"(d),"l"(s):"memory");
}
#define CP_COMMIT() asm volatile("cp.async.commit_group;" :::"memory")
#define CP_WAIT0()  asm volatile("cp.async.wait_group 0;" :::"memory")
#define CP_WAIT1()  asm volatile("cp.async.wait_group 1;" :::"memory")
__device__ __forceinline__ void sts32(uint32_t a, uint32_t v) {
  asm volatile("st.shared.b32 [%0], %1;" ::"r"(a),"r"(v):"memory");
}
__device__ __forceinline__ void ldm4(uint32_t a, uint32_t f[4]) {
  asm volatile("ldmatrix.sync.aligned.m8n8.x4.shared.b16 {%0,%1,%2,%3}, [%4];"
    : "=r"(f[0]),"=r"(f[1]),"=r"(f[2]),"=r"(f[3]) : "r"(a));
}
__device__ __forceinline__ void mma16816(float c[4], const uint32_t a[4], const uint32_t b0, const uint32_t b1) {
  asm volatile("mma.sync.aligned.m16n8k16.row.col.f32.bf16.bf16.f32 "
    "{%0,%1,%2,%3},{%4,%5,%6,%7},{%8,%9},{%0,%1,%2,%3};"
    : "+f"(c[0]),"+f"(c[1]),"+f"(c[2]),"+f"(c[3])
    : "r"(a[0]),"r"(a[1]),"r"(a[2]),"r"(a[3]),"r"(b0),"r"(b1));
}
__device__ __forceinline__ void mma16816h(float c[4], const uint32_t a[4], const uint32_t b0, const uint32_t b1) {
  asm volatile("mma.sync.aligned.m16n8k16.row.col.f32.f16.f16.f32 "
    "{%0,%1,%2,%3},{%4,%5,%6,%7},{%8,%9},{%0,%1,%2,%3};"
    : "+f"(c[0]),"+f"(c[1]),"+f"(c[2]),"+f"(c[3])
    : "r"(a[0]),"r"(a[1]),"r"(a[2]),"r"(a[3]),"r"(b0),"r"(b1));
}

// padded 16-bit tile: 128 rows x 136 cols
#define TPAD 136
#define TILE_B (128 * TPAD * 2)
#define OAH 0u
#define OAL (1u * TILE_B)
#define OBH (2u * TILE_B)
#define OBL (3u * TILE_B)
#define OB1H (4u * TILE_B)
#define OB1L (5u * TILE_B)
#define GEMM2_SM (6 * TILE_B)
#define GEMM_SM  (4 * TILE_B)
// qk layout: A=qh(1 tile) + kh/kl(jb0) + kh/kl(jb1) = 5 tiles
#define QKA  0u
#define QKB0H (1u * TILE_B)
#define QKB0L (2u * TILE_B)
#define QKB1H (3u * TILE_B)
#define QKB1L (4u * TILE_B)
#define QK_SM (5 * TILE_B)
#define SCAN2_SM (4 * TILE_B + 512)
#define POW_SM   (2 * 128 * 132 * 4)

// 256-thread tile loader (element size 2B, any 16-bit type)
__device__ __forceinline__ void load_tile(uint32_t sbt, const void* src_, int stride, int tid) {
  const __half* src = (const __half*)src_;
#pragma unroll
  for (int t = tid; t < 2048; t += 256) {
    int row = t >> 4, col = (t & 15) << 3;
    cp16(sbt + row * (TPAD * 2) + (col << 1), src + (size_t)row * stride + col);
  }
}

// pipelined 8-warp gemm pass (bf16): warp = 32m x 64n
__device__ __forceinline__ void gemm_pass(uint32_t sA, uint32_t sB, int lane, int wm, int wn,
                                          float acc[2][8][4]) {
  uint32_t aB0 = sA + (uint32_t)(((wm*32 + (lane & 15)) * TPAD + ((lane >> 4) << 3)) << 1);
  uint32_t aB1 = aB0 + (uint32_t)((16 * TPAD) << 1);
  uint32_t bB[4];
#pragma unroll
  for (int np = 0; np < 4; np++)
    bB[np] = sB + (uint32_t)(((wn*64 + np*16 + (lane & 7) + ((lane >> 4) << 3)) * TPAD + (lane & 8)) << 1);
  uint32_t afr[2][2][4];
  uint32_t bfr[2][4][4];
  ldm4(aB0, afr[0][0]);
  ldm4(aB1, afr[0][1]);
#pragma unroll
  for (int np = 0; np < 4; np++) ldm4(bB[np], bfr[0][np]);
#pragma unroll
  for (int ks = 0; ks < 8; ks++) {
    int cur = ks & 1, nxt = cur ^ 1;
    if (ks < 7) {
      uint32_t off = (uint32_t)((ks + 1) * 32);
      ldm4(aB0 + off, afr[nxt][0]);
      ldm4(aB1 + off, afr[nxt][1]);
#pragma unroll
      for (int np = 0; np < 4; np++) ldm4(bB[np] + off, bfr[nxt][np]);
    }
#pragma unroll
    for (int np = 0; np < 4; np++) {
#pragma unroll
      for (int mt = 0; mt < 2; mt++) {
        mma16816(acc[mt][np * 2],     afr[cur][mt], bfr[cur][np][0], bfr[cur][np][1]);
        mma16816(acc[mt][np * 2 + 1], afr[cur][mt], bfr[cur][np][2], bfr[cur][np][3]);
      }
    }
  }
}
// fp16 variant
__device__ __forceinline__ void gemm_pass_h(uint32_t sA, uint32_t sB, int lane, int wm, int wn,
                                            float acc[2][8][4]) {
  uint32_t aB0 = sA + (uint32_t)(((wm*32 + (lane & 15)) * TPAD + ((lane >> 4) << 3)) << 1);
  uint32_t aB1 = aB0 + (uint32_t)((16 * TPAD) << 1);
  uint32_t bB[4];
#pragma unroll
  for (int np = 0; np < 4; np++)
    bB[np] = sB + (uint32_t)(((wn*64 + np*16 + (lane & 7) + ((lane >> 4) << 3)) * TPAD + (lane & 8)) << 1);
  uint32_t afr[2][2][4];
  uint32_t bfr[2][4][4];
  ldm4(aB0, afr[0][0]);
  ldm4(aB1, afr[0][1]);
#pragma unroll
  for (int np = 0; np < 4; np++) ldm4(bB[np], bfr[0][np]);
#pragma unroll
  for (int ks = 0; ks < 8; ks++) {
    int cur = ks & 1, nxt = cur ^ 1;
    if (ks < 7) {
      uint32_t off = (uint32_t)((ks + 1) * 32);
      ldm4(aB0 + off, afr[nxt][0]);
      ldm4(aB1 + off, afr[nxt][1]);
#pragma unroll
      for (int np = 0; np < 4; np++) ldm4(bB[np] + off, bfr[nxt][np]);
    }
#pragma unroll
    for (int np = 0; np < 4; np++) {
#pragma unroll
      for (int mt = 0; mt < 2; mt++) {
        mma16816h(acc[mt][np * 2],     afr[cur][mt], bfr[cur][np][0], bfr[cur][np][1]);
        mma16816h(acc[mt][np * 2 + 1], afr[cur][mt], bfr[cur][np][2], bfr[cur][np][3]);
      }
    }
  }
}
__device__ __forceinline__ void gemm3v(uint32_t aH, uint32_t aL, uint32_t bH, uint32_t bL,
                                       int lane, int wm, int wn, float acc[2][8][4]) {
  gemm_pass(aH, bH, lane, wm, wn, acc);
  gemm_pass(aH, bL, lane, wm, wn, acc);
  gemm_pass(aL, bH, lane, wm, wn, acc);
}

__device__ __forceinline__ void split16(float x, __nv_bfloat16& h, __nv_bfloat16& l) {
  h = __float2bfloat16(x);
  l = __float2bfloat16(x - __bfloat162float(h));
}
__device__ __forceinline__ uint32_t packbf(__nv_bfloat16 lo_e, __nv_bfloat16 hi_e) {
  return ((uint32_t)__bfloat16_as_ushort(hi_e) << 16) | __bfloat16_as_ushort(lo_e);
}
__device__ __forceinline__ void split_store2(uint32_t sb, uint32_t offH, uint32_t offL,
                                             int r, int c0, float x0, float x1) {
  __nv_bfloat16 h0, l0, h1, l1;
  split16(x0, h0, l0); split16(x1, h1, l1);
  uint32_t off = (uint32_t)(r * TPAD + c0) << 1;
  sts32(sb + offH + off, packbf(h0, h1));
  sts32(sb + offL + off, packbf(l0, l1));
}

// ---------------- f32x2 mm (k_powers only — accuracy anchor) ----------------
__device__ __forceinline__ void mm128(const float* As, const float* Bs, int tx, int ty, ull acc[8][4]) {
#pragma unroll 4
  for (int kk = 0; kk < 128; kk++) {
    ull bp[4];
#pragma unroll
    for (int j = 0; j < 4; j++) bp[j] = *(const ull*)&Bs[kk*132 + tx*8 + j*2];
#pragma unroll
    for (int i = 0; i < 8; i++) {
      float a = As[(ty*8+i)*132 + kk];
      ull ap; asm("mov.b64 %0,{%1,%1};" : "=l"(ap) : "f"(a));
#pragma unroll
      for (int j = 0; j < 4; j++)
        asm("fma.rn.f32x2 %0,%1,%2,%0;" : "+l"(acc[i][j]) : "l"(ap), "l"(bp[j]));
    }
  }
}
__device__ __forceinline__ float2 upk(ull p) {
  float2 r; asm("mov.b64 {%0,%1}, %2;" : "=f"(r.x), "=f"(r.y) : "l"(p)); return r;
}

__global__ void k_init(const float* __restrict__ GA) {
  int m = blockIdx.x, n = threadIdx.x;
  g_PT[m*NS+n] = (m==n) ? 1.f : 0.f;
  g_PT[NS*NS + m*NS + n] = GA[n*NS + m];
}

// QTth[0]=I; Kth col 0 = split(GB); zero g_B (merged)
__global__ void k_prep_small(const float* __restrict__ GB) {
  int tid = threadIdx.x;
  __nv_bfloat16 one = __float2bfloat16(1.f), zero = __float2bfloat16(0.f);
  for (int l = tid; l < 8192; l += 256) {
    int n = l >> 6, k0 = (l & 63) * 2;
    uint32_t h = 0;
    if (n == k0) h = packbf(one, zero);
    else if (n == k0 + 1) h = packbf(zero, one);
    *(uint32_t*)(g_QTth + n*128 + k0) = h;
    *(uint32_t*)(g_QTtl + n*128 + k0) = 0;
  }
  if (tid < 128) {
    __nv_bfloat16 h, l;
    split16(GB[tid], h, l);
    g_Kth[tid*128 + 0] = h;
    g_Ktl[tid*128 + 0] = l;
  }
  for (int i = tid; i < 3*64*NS; i += 256) g_B[i] = 0.f;
}

__global__ __launch_bounds__(256) void k_powers_f(const float* __restrict__ GB) {
  extern __shared__ float sm[];
  float* R = sm;
  float* G = sm + 128*132;
  int b = blockIdx.x, tid = threadIdx.x, tx = tid & 15, ty = tid >> 4;
  int e; __nv_bfloat16 *dh, *dl;
  if (b < 128) { e = b + 1; dh = g_PTth + (size_t)(b+1)*NS*NS; dl = g_PTtl + (size_t)(b+1)*NS*NS; }
  else { int p = b - 127; e = p << 7; dh = g_QTth + (size_t)p*NS*NS; dl = g_QTtl + (size_t)p*NS*NS; }
  const float* GAT = g_PT + NS*NS;
  for (int l = tid; l < NS*NS; l += 256) {
    int r = l >> 7, c = l & 127;
    float v = GAT[l];
    G[r*132+c] = v; R[r*132+c] = v;
  }
  __syncthreads();
  int msb = 31 - __clz(e);
  for (int bit = msb - 1; bit >= 0; bit--) {
    {
      ull acc[8][4] = {};
      mm128(R, R, tx, ty, acc);
      __syncthreads();
#pragma unroll
      for (int i = 0; i < 8; i++)
#pragma unroll
        for (int j = 0; j < 4; j++) {
          float2 v = upk(acc[i][j]);
          R[(ty*8+i)*132 + tx*8 + j*2] = v.x;
          R[(ty*8+i)*132 + tx*8 + j*2 + 1] = v.y;
        }
      __syncthreads();
    }
    if ((e >> bit) & 1) {
      ull acc[8][4] = {};
      mm128(R, G, tx, ty, acc);
      __syncthreads();
#pragma unroll
      for (int i = 0; i < 8; i++)
#pragma unroll
        for (int j = 0; j < 4; j++) {
          float2 v = upk(acc[i][j]);
          R[(ty*8+i)*132 + tx*8 + j*2] = v.x;
          R[(ty*8+i)*132 + tx*8 + j*2 + 1] = v.y;
        }
      __syncthreads();
    }
  }
  for (int l = tid; l < 8192; l += 256) {
    int n = l >> 6, k0 = (l & 63) * 2;
    __nv_bfloat16 h0, l0, h1, l1;
    split16(R[k0*132 + n], h0, l0);
    split16(R[(k0+1)*132 + n], h1, l1);
    *(uint32_t*)(dh + (size_t)n*128 + k0) = packbf(h0, h1);
    *(uint32_t*)(dl + (size_t)n*128 + k0) = packbf(l0, l1);
  }
  if (b < 127 && tid < 128) {
    int n = tid;
    float acc = 0.f;
#pragma unroll 4
    for (int m = 0; m < 128; m++) acc = fmaf(R[m*132 + n], GB[m], acc);
    __nv_bfloat16 h, l;
    split16(acc, h, l);
    g_Kth[n*128 + (b+1)] = h;
    g_Ktl[n*128 + (b+1)] = l;
  }
}

// ---------------- scan GEMMs (bf16 3-pass, unchanged) ----------------
__global__ __launch_bounds__(256) void k_localconv_h(const float* __restrict__ fq,
                                                     const float* __restrict__ fk,
                                                     const float* __restrict__ fv) {
  extern __shared__ char dsm[];
  uint32_t sb = smem_u32(dsm);
  float* fs = (float*)(dsm + 4*TILE_B);
  int ci = blockIdx.x, ch = blockIdx.y;
  const float* f = (ch == 0) ? fq : ((ch == 1) ? fk : fv);
  int tid = threadIdx.x, lane = tid & 31, wid = tid >> 5;
  int wm = wid & 3, wn = wid >> 2;
  load_tile(sb + OBH, g_Kth, 128, tid);
  load_tile(sb + OBL, g_Ktl, 128, tid);
  CP_COMMIT();
  if (tid < 128) fs[tid] = f[ci*128 + tid];
  __syncthreads();
  for (int l = tid; l < 8192; l += 256) {
    int r = l >> 6, c0 = (l & 63) * 2;
    float x0 = (c0 <= r) ? fs[r - c0] : 0.f;
    float x1 = (c0 + 1 <= r) ? fs[r - c0 - 1] : 0.f;
    split_store2(sb, OAH, OAL, r, c0, x0, x1);
  }
  CP_WAIT0();
  __syncthreads();
  float acc[2][8][4] = {};
  gemm3v(sb + OAH, sb + OAL, sb + OBH, sb + OBL, lane, wm, wn, acc);
  float* Cc = g_cs + ((size_t)ch*SEQ + (size_t)ci*128) * NS;
#pragma unroll
  for (int mt = 0; mt < 2; mt++) {
    int r0 = wm*32 + mt*16 + (lane >> 2);
#pragma unroll
    for (int nt = 0; nt < 8; nt++) {
      int gc = wn*64 + nt*8 + 2*(lane & 3);
      *(float2*)(Cc + (size_t)r0*NS + gc)     = make_float2(acc[mt][nt][0], acc[mt][nt][1]);
      *(float2*)(Cc + (size_t)(r0+8)*NS + gc) = make_float2(acc[mt][nt][2], acc[mt][nt][3]);
      if (r0 + 8 == 127)
        *(float2*)(g_U + (size_t)(ch*64 + ci)*NS + gc) = make_float2(acc[mt][nt][2], acc[mt][nt][3]);
    }
  }
}

__global__ __launch_bounds__(256) void k_boundary_h() {
  extern __shared__ char dsm[];
  uint32_t sb = smem_u32(dsm);
  int p = blockIdx.x, rb = blockIdx.y;
  int tid = threadIdx.x, lane = tid & 31, wid = tid >> 5;
  int wm = wid & 3, wn = wid >> 2;
  load_tile(sb + OBH, g_QTth + (size_t)p*NS*NS, 128, tid);
  load_tile(sb + OBL, g_QTtl + (size_t)p*NS*NS, 128, tid);
  CP_COMMIT();
  for (int l = tid; l < 8192; l += 256) {
    int r = l >> 6, c0 = (l & 63) * 2;
    int gr = rb*128 + r;
    bool ok = (gr < 192) && ((gr & 63) >= p);
    float x0 = ok ? g_U[(size_t)(gr - p)*NS + c0] : 0.f;
    float x1 = ok ? g_U[(size_t)(gr - p)*NS + c0 + 1] : 0.f;
    split_store2(sb, OAH, OAL, r, c0, x0, x1);
  }
  CP_WAIT0();
  __syncthreads();
  float acc[2][8][4] = {};
  gemm3v(sb + OAH, sb + OAL, sb + OBH, sb + OBL, lane, wm, wn, acc);
#pragma unroll
  for (int mt = 0; mt < 2; mt++) {
    int r0 = wm*32 + mt*16 + (lane >> 2);
#pragma unroll
    for (int e2 = 0; e2 < 2; e2++) {
      int gr = rb*128 + r0 + e2*8;
      if (gr < 192 && (gr & 63) >= p) {
#pragma unroll
        for (int nt = 0; nt < 8; nt++) {
          int gc = wn*64 + nt*8 + 2*(lane & 3);
          atomicAdd(&g_B[(size_t)gr*NS + gc],     acc[mt][nt][e2*2]);
          atomicAdd(&g_B[(size_t)gr*NS + gc + 1], acc[mt][nt][e2*2 + 1]);
        }
      }
    }
  }
}

__global__ __launch_bounds__(256) void k_propagate_h() {
  extern __shared__ char dsm[];
  uint32_t sb = smem_u32(dsm);
  int r = blockIdx.x, rb = blockIdx.y;
  int tid = threadIdx.x, lane = tid & 31, wid = tid >> 5;
  int wm = wid & 3, wn = wid >> 2;
  load_tile(sb + OBH, g_PTth + (size_t)(r+1)*NS*NS, 128, tid);
  load_tile(sb + OBL, g_PTtl + (size_t)(r+1)*NS*NS, 128, tid);
  CP_COMMIT();
  for (int l = tid; l < 8192; l += 256) {
    int rr = l >> 6, c0 = (l & 63) * 2;
    int gr = rb*128 + rr;
    float x0 = (gr < 192) ? g_B[(size_t)gr*NS + c0] : 0.f;
    float x1 = (gr < 192) ? g_B[(size_t)gr*NS + c0 + 1] : 0.f;
    split_store2(sb, OAH, OAL, rr, c0, x0, x1);
  }
  CP_WAIT0();
  __syncthreads();
  float acc[2][8][4] = {};
  gemm3v(sb + OAH, sb + OAL, sb + OBH, sb + OBL, lane, wm, wn, acc);
#pragma unroll
  for (int mt = 0; mt < 2; mt++) {
    int r0 = wm*32 + mt*16 + (lane >> 2);
#pragma unroll
    for (int e2 = 0; e2 < 2; e2++) {
      int gr = rb*128 + r0 + e2*8;
      if (gr < 192 && (gr & 63) < 63) {
        int ch = gr >> 6, ic = (gr & 63) + 1;
        float* dst = &g_cs[((size_t)ch*SEQ + (size_t)ic*128 + r) * NS];
#pragma unroll
        for (int nt = 0; nt < 8; nt++) {
          int gc = wn*64 + nt*8 + 2*(lane & 3);
          dst[gc]     += acc[mt][nt][e2*2];
          dst[gc + 1] += acc[mt][nt][e2*2 + 1];
        }
      }
    }
  }
}

// ---------------- preps ----------------
__global__ void k_prep_qk() {
  size_t idx = (size_t)blockIdx.x * 256 + threadIdx.x;
  float x = g_cs[idx];
  size_t SN = (size_t)SEQ * NS;
  if (idx < SN) {
    g_qh[idx] = __float2half_rn(x);           // q: hi only (2-pass drops ql)
  } else {
    __half h = __float2half_rn(x);
    g_kh[idx - SN] = h;
    g_kl[idx - SN] = __float2half_rn(x - __half2float(h));
  }
}
__global__ void k_prep_vt() {
  __shared__ float t[32][33];
  int t0 = blockIdx.x * 32, n0 = blockIdx.y * 32;
  int tx = threadIdx.x, ty = threadIdx.y;
  const float* v = g_cs + (size_t)2 * SEQ * NS;
#pragma unroll
  for (int j = 0; j < 32; j += 8) t[ty+j][tx] = v[(size_t)(t0 + ty + j)*NS + n0 + tx];
  __syncthreads();
#pragma unroll
  for (int j = 0; j < 32; j += 8) {
    __nv_bfloat16 h, l;
    split16(t[tx][ty+j], h, l);
    size_t o = (size_t)(n0 + ty + j) * SEQ + t0 + tx;
    g_vth[o] = h; g_vtl[o] = l;
  }
}
__global__ void k_prep_wpt(const float* __restrict__ Wp) {
  __shared__ float t[32][33];
  int n0 = blockIdx.x * 32, k0 = blockIdx.y * 32;
  int tx = threadIdx.x, ty = threadIdx.y;
#pragma unroll
  for (int j = 0; j < 32; j += 8) {
    int n = n0 + tx;
    t[ty+j][tx] = (n < OUTD) ? Wp[(size_t)(k0 + ty + j)*OUTD + n] : 0.f;
  }
  __syncthreads();
#pragma unroll
  for (int j = 0; j < 32; j += 8) {
    __nv_bfloat16 h, l;
    split16(t[tx][ty+j], h, l);
    size_t o = (size_t)(n0 + ty + j) * NS + k0 + tx;
    g_wph[o] = h; g_wpl[o] = l;
  }
}

// ---------------- QK^T (fp16 2-pass, 2 K-tiles/CTA) + fused stats ----------------
__device__ __forceinline__ void qk_epilogue(float* __restrict__ S, int ib, int jb,
                                            int wm, int wn, int lane, float acc[2][8][4]) {
#pragma unroll
  for (int mt = 0; mt < 2; mt++)
#pragma unroll
    for (int nt = 0; nt < 8; nt++)
#pragma unroll
      for (int e = 0; e < 4; e++) acc[mt][nt][e] *= 0.25f;
  int jc = jb * 2 + wn;
#pragma unroll
  for (int mt = 0; mt < 2; mt++) {
    int r0 = ib*128 + wm*32 + mt*16 + (lane >> 2);
    float mx0 = -3.4e38f, mx1 = -3.4e38f;
#pragma unroll
    for (int nt = 0; nt < 8; nt++) {
      mx0 = fmaxf(mx0, fmaxf(acc[mt][nt][0], acc[mt][nt][1]));
      mx1 = fmaxf(mx1, fmaxf(acc[mt][nt][2], acc[mt][nt][3]));
    }
    mx0 = fmaxf(mx0, __shfl_xor_sync(~0u, mx0, 1));
    mx0 = fmaxf(mx0, __shfl_xor_sync(~0u, mx0, 2));
    mx1 = fmaxf(mx1, __shfl_xor_sync(~0u, mx1, 1));
    mx1 = fmaxf(mx1, __shfl_xor_sync(~0u, mx1, 2));
    float s0 = 0.f, s1 = 0.f;
#pragma unroll
    for (int nt = 0; nt < 8; nt++) {
      s0 += __expf(acc[mt][nt][0] - mx0) + __expf(acc[mt][nt][1] - mx0);
      s1 += __expf(acc[mt][nt][2] - mx1) + __expf(acc[mt][nt][3] - mx1);
    }
    s0 += __shfl_xor_sync(~0u, s0, 1); s0 += __shfl_xor_sync(~0u, s0, 2);
    s1 += __shfl_xor_sync(~0u, s1, 1); s1 += __shfl_xor_sync(~0u, s1, 2);
    if ((lane & 3) == 0) {
      g_tmax[(size_t)jc*SEQ + r0] = mx0;     g_tsum[(size_t)jc*SEQ + r0] = s0;
      g_tmax[(size_t)jc*SEQ + r0 + 8] = mx1; g_tsum[(size_t)jc*SEQ + r0 + 8] = s1;
    }
    int colb = jb*128 + wn*64 + 2*(lane & 3);
#pragma unroll
    for (int nt = 0; nt < 8; nt++) {
      *(float2*)(S + (size_t)r0*SEQ + colb + nt*8)     = make_float2(acc[mt][nt][0], acc[mt][nt][1]);
      *(float2*)(S + (size_t)(r0+8)*SEQ + colb + nt*8) = make_float2(acc[mt][nt][2], acc[mt][nt][3]);
    }
  }
}

__global__ __launch_bounds__(256) void k_qk_mma(float* __restrict__ S) {
  extern __shared__ char dsm[];
  uint32_t sb = smem_u32(dsm);
  int tid = threadIdx.x, lane = tid & 31, wid = tid >> 5;
  int wm = wid & 3, wn = wid >> 2;
  int ib = blockIdx.x, jb0 = blockIdx.y * 2, jb1 = jb0 + 1;

  load_tile(sb + QKA,   g_qh + (size_t)ib*128*NS, NS, tid);
  load_tile(sb + QKB0H, g_kh + (size_t)jb0*128*NS, NS, tid);
  load_tile(sb + QKB0L, g_kl + (size_t)jb0*128*NS, NS, tid);
  CP_COMMIT();
  load_tile(sb + QKB1H, g_kh + (size_t)jb1*128*NS, NS, tid);
  load_tile(sb + QKB1L, g_kl + (size_t)jb1*128*NS, NS, tid);
  CP_COMMIT();
  CP_WAIT1();
  __syncthreads();
  {
    float acc[2][8][4] = {};
    gemm_pass_h(sb + QKA, sb + QKB0H, lane, wm, wn, acc);
    gemm_pass_h(sb + QKA, sb + QKB0L, lane, wm, wn, acc);
    qk_epilogue(S, ib, jb0, wm, wn, lane, acc);
  }
  CP_WAIT0();
  __syncthreads();
  {
    float acc[2][8][4] = {};
    gemm_pass_h(sb + QKA, sb + QKB1H, lane, wm, wn, acc);
    gemm_pass_h(sb + QKA, sb + QKB1L, lane, wm, wn, acc);
    qk_epilogue(S, ib, jb1, wm, wn, lane, acc);
  }
}

__global__ void k_combine() {
  int row = blockIdx.x * 256 + threadIdx.x;
  float mx = -3.4e38f;
  for (int j = 0; j < 128; j++) mx = fmaxf(mx, g_tmax[(size_t)j*SEQ + row]);
  float s = 0.f;
  for (int j = 0; j < 128; j++) s += g_tsum[(size_t)j*SEQ + row] * __expf(g_tmax[(size_t)j*SEQ + row] - mx);
  g_RM[row] = mx;
  g_RSI[row] = 1.0f / s;
}

// ---------------- softmax + attn write + attn@V (bf16 3-pass, unchanged) ----------------
__global__ __launch_bounds__(256) void k_ctx_mma(float* __restrict__ S) {
  extern __shared__ char dsm[];
  uint32_t sb = smem_u32(dsm);
  int tid = threadIdx.x, lane = tid & 31, wid = tid >> 5;
  int wm = wid & 3, wn = wid >> 2;
  int ib = blockIdx.x, sp = blockIdx.y;

  int crow = tid >> 1;
  int cbase = (tid & 1) * 64;
  float m = g_RM[ib*128 + crow];
  float li = g_RSI[ib*128 + crow];

  load_tile(sb + OBH, g_vth + sp*1024, SEQ, tid);
  load_tile(sb + OBL, g_vtl + sp*1024, SEQ, tid);
  CP_COMMIT();

  float acc[2][8][4] = {};
  for (int c = 0; c < 8; c++) {
    uint32_t bH = (c & 1) ? OB1H : OBH;
    uint32_t bL = (c & 1) ? OB1L : OBL;
    if (c < 7) {
      uint32_t nH = (c & 1) ? OBH : OB1H;
      uint32_t nL = (c & 1) ? OBL : OB1L;
      int kn = sp*1024 + (c+1)*128;
      load_tile(sb + nH, g_vth + kn, SEQ, tid);
      load_tile(sb + nL, g_vtl + kn, SEQ, tid);
      CP_COMMIT();
    }
    int k0 = sp*1024 + c*128;
    float2* srow = (float2*)(S + (size_t)(ib*128 + crow)*SEQ + k0 + cbase);
    uint32_t abase = sb + (uint32_t)((crow * TPAD + cbase) << 1);
#pragma unroll 8
    for (int i = 0; i < 32; i++) {
      float2 s2 = srow[i];
      float a0 = __expf(s2.x - m) * li;
      float a1 = __expf(s2.y - m) * li;
      srow[i] = make_float2(a0, a1);
      __nv_bfloat16 h0, l0, h1, l1;
      split16(a0, h0, l0); split16(a1, h1, l1);
      sts32(abase + OAH + i*4, packbf(h0, h1));
      sts32(abase + OAL + i*4, packbf(l0, l1));
    }
    if (c < 7) CP_WAIT1(); else CP_WAIT0();
    __syncthreads();
    gemm3v(sb + OAH, sb + OAL, sb + bH, sb + bL, lane, wm, wn, acc);
    __syncthreads();
  }
#pragma unroll
  for (int mt = 0; mt < 2; mt++) {
    int r0 = ib*128 + wm*32 + mt*16 + (lane >> 2);
    int colb = wn*64 + 2*(lane & 3);
#pragma unroll
    for (int nt = 0; nt < 8; nt++) {
      *(float2*)(g_ctxp + ((size_t)sp*SEQ + r0)*NS + colb + nt*8)     = make_float2(acc[mt][nt][0], acc[mt][nt][1]);
      *(float2*)(g_ctxp + ((size_t)sp*SEQ + r0 + 8)*NS + colb + nt*8) = make_float2(acc[mt][nt][2], acc[mt][nt][3]);
    }
  }
}

__global__ void k_ctxred() {
  size_t idx = (size_t)blockIdx.x * 256 + threadIdx.x;
  float acc = 0.f;
#pragma unroll
  for (int s = 0; s < 8; s++) acc += g_ctxp[(size_t)s*SEQ*NS + idx];
  __nv_bfloat16 h, l;
  split16(acc, h, l);
  g_ch[idx] = h; g_clo[idx] = l;
}

// ---------------- out = ctx @ Wp + bp (bf16 3-pass) ----------------
__global__ __launch_bounds__(256) void k_out_mma(float* __restrict__ out, const float* __restrict__ bp) {
  extern __shared__ char dsm[];
  uint32_t sb = smem_u32(dsm);
  int tid = threadIdx.x, lane = tid & 31, wid = tid >> 5;
  int wm = wid & 3, wn = wid >> 2;
  int ib = blockIdx.x, cb = blockIdx.y;

  load_tile(sb + OAH, g_ch  + (size_t)ib*128*NS, NS, tid);
  load_tile(sb + OAL, g_clo + (size_t)ib*128*NS, NS, tid);
  load_tile(sb + OBH, g_wph + (size_t)cb*128*NS, NS, tid);
  load_tile(sb + OBL, g_wpl + (size_t)cb*128*NS, NS, tid);
  CP_COMMIT(); CP_WAIT0();
  __syncthreads();

  float acc[2][8][4] = {};
  gemm3v(sb + OAH, sb + OAL, sb + OBH, sb + OBL, lane, wm, wn, acc);

#pragma unroll
  for (int mt = 0; mt < 2; mt++) {
    int r0 = ib*128 + wm*32 + mt*16 + (lane >> 2);
#pragma unroll
    for (int nt = 0; nt < 8; nt++) {
      int gc = cb*128 + wn*64 + nt*8 + 2*(lane & 3);
      if (gc + 1 < OUTD) {
        out[(size_t)r0*OUTD + gc]         = acc[mt][nt][0] + bp[gc];
        out[(size_t)r0*OUTD + gc + 1]     = acc[mt][nt][1] + bp[gc + 1];
        out[(size_t)(r0+8)*OUTD + gc]     = acc[mt][nt][2] + bp[gc];
        out[(size_t)(r0+8)*OUTD + gc + 1] = acc[mt][nt][3] + bp[gc + 1];
      } else if (gc < OUTD) {
        out[(size_t)r0*OUTD + gc]     = acc[mt][nt][0] + bp[gc];
        out[(size_t)(r0+8)*OUTD + gc] = acc[mt][nt][2] + bp[gc];
      }
    }
  }
}

// ---------------- launch ----------------
extern "C" void kernel_launch(void* const* d_in, const int* in_sizes, int n_in,
                              void* d_out, int out_size) {
  const float* q  = (const float*)d_in[0];
  const float* kk = (const float*)d_in[1];
  const float* vv = (const float*)d_in[2];
  const float* GA = (const float*)d_in[3];
  const float* GB = (const float*)d_in[4];
  const float* Wp = (const float*)d_in[5];
  const float* bp = (const float*)d_in[6];
  float* out = (float*)d_out;

  cudaFuncSetAttribute(k_powers_f,    cudaFuncAttributeMaxDynamicSharedMemorySize, POW_SM);
  cudaFuncSetAttribute(k_localconv_h, cudaFuncAttributeMaxDynamicSharedMemorySize, SCAN2_SM);
  cudaFuncSetAttribute(k_boundary_h,  cudaFuncAttributeMaxDynamicSharedMemorySize, SCAN2_SM);
  cudaFuncSetAttribute(k_propagate_h, cudaFuncAttributeMaxDynamicSharedMemorySize, SCAN2_SM);
  cudaFuncSetAttribute(k_qk_mma,      cudaFuncAttributeMaxDynamicSharedMemorySize, QK_SM);
  cudaFuncSetAttribute(k_ctx_mma,     cudaFuncAttributeMaxDynamicSharedMemorySize, GEMM2_SM);
  cudaFuncSetAttribute(k_out_mma,     cudaFuncAttributeMaxDynamicSharedMemorySize, GEMM_SM);

  float* pFB;
  cudaGetSymbolAddress((void**)&pFB, g_attn_fb);
  float* S = (out_size >= (int)((size_t)SEQ*OUTD + (size_t)SEQ*SEQ)) ? out + (size_t)SEQ*OUTD : pFB;

  k_prep_wpt<<<dim3(32, 4), dim3(32, 8)>>>(Wp);          // 0 (no deps beyond Wp)
  k_init<<<128, 128>>>(GA);                              // 1
  k_prep_small<<<1, 256>>>(GB);                          // 2 (+ zero g_B)
  k_powers_f<<<191, 256, POW_SM>>>(GB);                  // 3 ← ncu profiled slot
  k_localconv_h<<<dim3(64, 3), 256, SCAN2_SM>>>(q, kk, vv);
  k_boundary_h<<<dim3(64, 2), 256, SCAN2_SM>>>();
  k_propagate_h<<<dim3(128, 2), 256, SCAN2_SM>>>();
  k_prep_qk<<<8192, 256>>>();
  k_prep_vt<<<dim3(256, 4), dim3(32, 8)>>>();
  k_qk_mma<<<dim3(64, 32), 256, QK_SM>>>(S);
  k_combine<<<32, 256>>>();
  k_ctx_mma<<<dim3(64, 8), 256, GEMM2_SM>>>(S);
  k_ctxred<<<4096, 256>>>();
  k_out_mma<<<dim3(64, 8), 256, GEMM_SM>>>(out, bp);
}

// round 15
// speedup vs baseline: 1.1938x; 1.0433x over previous
#include <cuda_runtime.h>
#include <cuda_bf16.h>
#include <cuda_fp16.h>
#include <math.h>
#include <stdint.h>
typedef unsigned long long ull;

#define NS   128
#define SEQ  8192
#define OUTD 1000

// ---------------- device scratch ----------------
__device__ float g_PT[(size_t)2 * NS * NS];
__device__ float g_cs[(size_t)3 * SEQ * NS];
__device__ float g_U[3 * 64 * NS];
__device__ float g_B[3 * 64 * NS];
__device__ float g_ctxp[(size_t)8 * SEQ * NS];
__device__ float g_attn_fb[(size_t)SEQ * SEQ];
__device__ float g_tmax[(size_t)128 * SEQ];
__device__ float g_tsum[(size_t)128 * SEQ];
__device__ float g_RM[SEQ];
__device__ float g_RSI[SEQ];
// fp16 q (hi only) and k (hi/lo) for 2-pass qk
__device__ __align__(256) __half g_qh[(size_t)SEQ * NS];
__device__ __align__(256) __half g_kh[(size_t)SEQ * NS], g_kl[(size_t)SEQ * NS];
// fp16 V hi/lo for 2-pass ctx
__device__ __align__(256) __half g_vth[(size_t)NS * SEQ], g_vtl[(size_t)NS * SEQ];
// bf16 for out (3-pass)
__device__ __align__(256) __nv_bfloat16 g_ch[(size_t)SEQ * NS], g_clo[(size_t)SEQ * NS];
__device__ __align__(256) __nv_bfloat16 g_wph[(size_t)1024 * NS], g_wpl[(size_t)1024 * NS];
__device__ __align__(256) __nv_bfloat16 g_PTth[(size_t)129 * NS * NS], g_PTtl[(size_t)129 * NS * NS];
__device__ __align__(256) __nv_bfloat16 g_QTth[(size_t)64 * NS * NS],  g_QTtl[(size_t)64 * NS * NS];
__device__ __align__(256) __nv_bfloat16 g_Kth[NS * NS], g_Ktl[NS * NS];

// ---------------- PTX helpers ----------------
__device__ __forceinline__ uint32_t smem_u32(const void* p) {
  uint32_t a;
  asm("{ .reg .u64 t; cvta.to.shared.u64 t, %1; cvt.u32.u64 %0, t; }" : "=r"(a) : "l"(p));
  return a;
}
__device__ __forceinline__ void cp16(uint32_t d, const void* s) {
  asm volatile("cp.async.cg.shared.global [%0], [%1], 16;" ::"r"(d),"l"(s):"memory");
}
#define CP_COMMIT() asm volatile("cp.async.commit_group;" :::"memory")
#define CP_WAIT0()  asm volatile("cp.async.wait_group 0;" :::"memory")
#define CP_WAIT1()  asm volatile("cp.async.wait_group 1;" :::"memory")
__device__ __forceinline__ void sts32(uint32_t a, uint32_t v) {
  asm volatile("st.shared.b32 [%0], %1;" ::"r"(a),"r"(v):"memory");
}
__device__ __forceinline__ void ldm4(uint32_t a, uint32_t f[4]) {
  asm volatile("ldmatrix.sync.aligned.m8n8.x4.shared.b16 {%0,%1,%2,%3}, [%4];"
    : "=r"(f[0]),"=r"(f[1]),"=r"(f[2]),"=r"(f[3]) : "r"(a));
}
__device__ __forceinline__ void mma16816(float c[4], const uint32_t a[4], const uint32_t b0, const uint32_t b1) {
  asm volatile("mma.sync.aligned.m16n8k16.row.col.f32.bf16.bf16.f32 "
    "{%0,%1,%2,%3},{%4,%5,%6,%7},{%8,%9},{%0,%1,%2,%3};"
    : "+f"(c[0]),"+f"(c[1]),"+f"(c[2]),"+f"(c[3])
    : "r"(a[0]),"r"(a[1]),"r"(a[2]),"r"(a[3]),"r"(b0),"r"(b1));
}
__device__ __forceinline__ void mma16816h(float c[4], const uint32_t a[4], const uint32_t b0, const uint32_t b1) {
  asm volatile("mma.sync.aligned.m16n8k16.row.col.f32.f16.f16.f32 "
    "{%0,%1,%2,%3},{%4,%5,%6,%7},{%8,%9},{%0,%1,%2,%3};"
    : "+f"(c[0]),"+f"(c[1]),"+f"(c[2]),"+f"(c[3])
    : "r"(a[0]),"r"(a[1]),"r"(a[2]),"r"(a[3]),"r"(b0),"r"(b1));
}

// padded 16-bit tile: 128 rows x 136 cols
#define TPAD 136
#define TILE_B (128 * TPAD * 2)
#define OAH 0u
#define OAL (1u * TILE_B)
#define OBH (2u * TILE_B)
#define OBL (3u * TILE_B)
#define GEMM_SM  (4 * TILE_B)
// qk layout: A=qh + kh/kl(jb0) + kh/kl(jb1) = 5 tiles
#define QKA  0u
#define QKB0H (1u * TILE_B)
#define QKB0L (2u * TILE_B)
#define QKB1H (3u * TILE_B)
#define QKB1L (4u * TILE_B)
#define QK_SM (5 * TILE_B)
// ctx layout: A(attn fp16 hi) + V hi/lo double-buffered = 5 tiles
#define CTA_A 0u
#define CVH0 (1u * TILE_B)
#define CVL0 (2u * TILE_B)
#define CVH1 (3u * TILE_B)
#define CVL1 (4u * TILE_B)
#define CTX_SM (5 * TILE_B)
#define SCAN2_SM (4 * TILE_B + 512)
#define POW_SM   (2 * 128 * 132 * 4)

// 256-thread tile loader (element size 2B, any 16-bit type)
__device__ __forceinline__ void load_tile(uint32_t sbt, const void* src_, int stride, int tid) {
  const __half* src = (const __half*)src_;
#pragma unroll
  for (int t = tid; t < 2048; t += 256) {
    int row = t >> 4, col = (t & 15) << 3;
    cp16(sbt + row * (TPAD * 2) + (col << 1), src + (size_t)row * stride + col);
  }
}

// pipelined 8-warp gemm pass (bf16): warp = 32m x 64n
__device__ __forceinline__ void gemm_pass(uint32_t sA, uint32_t sB, int lane, int wm, int wn,
                                          float acc[2][8][4]) {
  uint32_t aB0 = sA + (uint32_t)(((wm*32 + (lane & 15)) * TPAD + ((lane >> 4) << 3)) << 1);
  uint32_t aB1 = aB0 + (uint32_t)((16 * TPAD) << 1);
  uint32_t bB[4];
#pragma unroll
  for (int np = 0; np < 4; np++)
    bB[np] = sB + (uint32_t)(((wn*64 + np*16 + (lane & 7) + ((lane >> 4) << 3)) * TPAD + (lane & 8)) << 1);
  uint32_t afr[2][2][4];
  uint32_t bfr[2][4][4];
  ldm4(aB0, afr[0][0]);
  ldm4(aB1, afr[0][1]);
#pragma unroll
  for (int np = 0; np < 4; np++) ldm4(bB[np], bfr[0][np]);
#pragma unroll
  for (int ks = 0; ks < 8; ks++) {
    int cur = ks & 1, nxt = cur ^ 1;
    if (ks < 7) {
      uint32_t off = (uint32_t)((ks + 1) * 32);
      ldm4(aB0 + off, afr[nxt][0]);
      ldm4(aB1 + off, afr[nxt][1]);
#pragma unroll
      for (int np = 0; np < 4; np++) ldm4(bB[np] + off, bfr[nxt][np]);
    }
#pragma unroll
    for (int np = 0; np < 4; np++) {
#pragma unroll
      for (int mt = 0; mt < 2; mt++) {
        mma16816(acc[mt][np * 2],     afr[cur][mt], bfr[cur][np][0], bfr[cur][np][1]);
        mma16816(acc[mt][np * 2 + 1], afr[cur][mt], bfr[cur][np][2], bfr[cur][np][3]);
      }
    }
  }
}
// fp16 variant
__device__ __forceinline__ void gemm_pass_h(uint32_t sA, uint32_t sB, int lane, int wm, int wn,
                                            float acc[2][8][4]) {
  uint32_t aB0 = sA + (uint32_t)(((wm*32 + (lane & 15)) * TPAD + ((lane >> 4) << 3)) << 1);
  uint32_t aB1 = aB0 + (uint32_t)((16 * TPAD) << 1);
  uint32_t bB[4];
#pragma unroll
  for (int np = 0; np < 4; np++)
    bB[np] = sB + (uint32_t)(((wn*64 + np*16 + (lane & 7) + ((lane >> 4) << 3)) * TPAD + (lane & 8)) << 1);
  uint32_t afr[2][2][4];
  uint32_t bfr[2][4][4];
  ldm4(aB0, afr[0][0]);
  ldm4(aB1, afr[0][1]);
#pragma unroll
  for (int np = 0; np < 4; np++) ldm4(bB[np], bfr[0][np]);
#pragma unroll
  for (int ks = 0; ks < 8; ks++) {
    int cur = ks & 1, nxt = cur ^ 1;
    if (ks < 7) {
      uint32_t off = (uint32_t)((ks + 1) * 32);
      ldm4(aB0 + off, afr[nxt][0]);
      ldm4(aB1 + off, afr[nxt][1]);
#pragma unroll
      for (int np = 0; np < 4; np++) ldm4(bB[np] + off, bfr[nxt][np]);
    }
#pragma unroll
    for (int np = 0; np < 4; np++) {
#pragma unroll
      for (int mt = 0; mt < 2; mt++) {
        mma16816h(acc[mt][np * 2],     afr[cur][mt], bfr[cur][np][0], bfr[cur][np][1]);
        mma16816h(acc[mt][np * 2 + 1], afr[cur][mt], bfr[cur][np][2], bfr[cur][np][3]);
      }
    }
  }
}
__device__ __forceinline__ void gemm3v(uint32_t aH, uint32_t aL, uint32_t bH, uint32_t bL,
                                       int lane, int wm, int wn, float acc[2][8][4]) {
  gemm_pass(aH, bH, lane, wm, wn, acc);
  gemm_pass(aH, bL, lane, wm, wn, acc);
  gemm_pass(aL, bH, lane, wm, wn, acc);
}

__device__ __forceinline__ void split16(float x, __nv_bfloat16& h, __nv_bfloat16& l) {
  h = __float2bfloat16(x);
  l = __float2bfloat16(x - __bfloat162float(h));
}
__device__ __forceinline__ uint32_t packbf(__nv_bfloat16 lo_e, __nv_bfloat16 hi_e) {
  return ((uint32_t)__bfloat16_as_ushort(hi_e) << 16) | __bfloat16_as_ushort(lo_e);
}
__device__ __forceinline__ uint32_t packh(__half lo_e, __half hi_e) {
  return ((uint32_t)__half_as_ushort(hi_e) << 16) | __half_as_ushort(lo_e);
}
__device__ __forceinline__ void split_store2(uint32_t sb, uint32_t offH, uint32_t offL,
                                             int r, int c0, float x0, float x1) {
  __nv_bfloat16 h0, l0, h1, l1;
  split16(x0, h0, l0); split16(x1, h1, l1);
  uint32_t off = (uint32_t)(r * TPAD + c0) << 1;
  sts32(sb + offH + off, packbf(h0, h1));
  sts32(sb + offL + off, packbf(l0, l1));
}

// ---------------- f32x2 mm (k_powers only — accuracy anchor; kk-paired A loads) ----------------
__device__ __forceinline__ float2 upk(ull p) {
  float2 r; asm("mov.b64 {%0,%1}, %2;" : "=f"(r.x), "=f"(r.y) : "l"(p)); return r;
}
__device__ __forceinline__ void mm128(const float* As, const float* Bs, int tx, int ty, ull acc[8][4]) {
#pragma unroll 2
  for (int kk = 0; kk < 128; kk += 2) {
    ull bp0[4], bp1[4];
#pragma unroll
    for (int j = 0; j < 4; j++) {
      bp0[j] = *(const ull*)&Bs[kk*132 + tx*8 + j*2];
      bp1[j] = *(const ull*)&Bs[(kk+1)*132 + tx*8 + j*2];
    }
#pragma unroll
    for (int i = 0; i < 8; i++) {
      float2 a2 = upk(*(const ull*)&As[(ty*8+i)*132 + kk]);
      ull ap0, ap1;
      asm("mov.b64 %0,{%1,%1};" : "=l"(ap0) : "f"(a2.x));
      asm("mov.b64 %0,{%1,%1};" : "=l"(ap1) : "f"(a2.y));
#pragma unroll
      for (int j = 0; j < 4; j++) {
        asm("fma.rn.f32x2 %0,%1,%2,%0;" : "+l"(acc[i][j]) : "l"(ap0), "l"(bp0[j]));
        asm("fma.rn.f32x2 %0,%1,%2,%0;" : "+l"(acc[i][j]) : "l"(ap1), "l"(bp1[j]));
      }
    }
  }
}

__global__ void k_init(const float* __restrict__ GA) {
  int m = blockIdx.x, n = threadIdx.x;
  g_PT[m*NS+n] = (m==n) ? 1.f : 0.f;
  g_PT[NS*NS + m*NS + n] = GA[n*NS + m];
}

// QTth[0]=I; Kth col 0 = split(GB); zero g_B
__global__ void k_prep_small(const float* __restrict__ GB) {
  int tid = threadIdx.x;
  __nv_bfloat16 one = __float2bfloat16(1.f), zero = __float2bfloat16(0.f);
  for (int l = tid; l < 8192; l += 256) {
    int n = l >> 6, k0 = (l & 63) * 2;
    uint32_t h = 0;
    if (n == k0) h = packbf(one, zero);
    else if (n == k0 + 1) h = packbf(zero, one);
    *(uint32_t*)(g_QTth + n*128 + k0) = h;
    *(uint32_t*)(g_QTtl + n*128 + k0) = 0;
  }
  if (tid < 128) {
    __nv_bfloat16 h, l;
    split16(GB[tid], h, l);
    g_Kth[tid*128 + 0] = h;
    g_Ktl[tid*128 + 0] = l;
  }
  for (int i = tid; i < 3*64*NS; i += 256) g_B[i] = 0.f;
}

__global__ __launch_bounds__(256) void k_powers_f(const float* __restrict__ GB) {
  extern __shared__ float sm[];
  float* R = sm;
  float* G = sm + 128*132;
  int b = blockIdx.x, tid = threadIdx.x, tx = tid & 15, ty = tid >> 4;
  int e; __nv_bfloat16 *dh, *dl;
  if (b < 128) { e = b + 1; dh = g_PTth + (size_t)(b+1)*NS*NS; dl = g_PTtl + (size_t)(b+1)*NS*NS; }
  else { int p = b - 127; e = p << 7; dh = g_QTth + (size_t)p*NS*NS; dl = g_QTtl + (size_t)p*NS*NS; }
  const float* GAT = g_PT + NS*NS;
  for (int l = tid; l < NS*NS; l += 256) {
    int r = l >> 7, c = l & 127;
    float v = GAT[l];
    G[r*132+c] = v; R[r*132+c] = v;
  }
  __syncthreads();
  int msb = 31 - __clz(e);
  for (int bit = msb - 1; bit >= 0; bit--) {
    {
      ull acc[8][4] = {};
      mm128(R, R, tx, ty, acc);
      __syncthreads();
#pragma unroll
      for (int i = 0; i < 8; i++)
#pragma unroll
        for (int j = 0; j < 4; j++) {
          float2 v = upk(acc[i][j]);
          R[(ty*8+i)*132 + tx*8 + j*2] = v.x;
          R[(ty*8+i)*132 + tx*8 + j*2 + 1] = v.y;
        }
      __syncthreads();
    }
    if ((e >> bit) & 1) {
      ull acc[8][4] = {};
      mm128(R, G, tx, ty, acc);
      __syncthreads();
#pragma unroll
      for (int i = 0; i < 8; i++)
#pragma unroll
        for (int j = 0; j < 4; j++) {
          float2 v = upk(acc[i][j]);
          R[(ty*8+i)*132 + tx*8 + j*2] = v.x;
          R[(ty*8+i)*132 + tx*8 + j*2 + 1] = v.y;
        }
      __syncthreads();
    }
  }
  for (int l = tid; l < 8192; l += 256) {
    int n = l >> 6, k0 = (l & 63) * 2;
    __nv_bfloat16 h0, l0, h1, l1;
    split16(R[k0*132 + n], h0, l0);
    split16(R[(k0+1)*132 + n], h1, l1);
    *(uint32_t*)(dh + (size_t)n*128 + k0) = packbf(h0, h1);
    *(uint32_t*)(dl + (size_t)n*128 + k0) = packbf(l0, l1);
  }
  if (b < 127 && tid < 128) {
    int n = tid;
    float acc = 0.f;
#pragma unroll 4
    for (int m = 0; m < 128; m++) acc = fmaf(R[m*132 + n], GB[m], acc);
    __nv_bfloat16 h, l;
    split16(acc, h, l);
    g_Kth[n*128 + (b+1)] = h;
    g_Ktl[n*128 + (b+1)] = l;
  }
}

// ---------------- scan GEMMs (bf16 3-pass) ----------------
__global__ __launch_bounds__(256) void k_localconv_h(const float* __restrict__ fq,
                                                     const float* __restrict__ fk,
                                                     const float* __restrict__ fv) {
  extern __shared__ char dsm[];
  uint32_t sb = smem_u32(dsm);
  float* fs = (float*)(dsm + 4*TILE_B);
  int ci = blockIdx.x, ch = blockIdx.y;
  const float* f = (ch == 0) ? fq : ((ch == 1) ? fk : fv);
  int tid = threadIdx.x, lane = tid & 31, wid = tid >> 5;
  int wm = wid & 3, wn = wid >> 2;
  load_tile(sb + OBH, g_Kth, 128, tid);
  load_tile(sb + OBL, g_Ktl, 128, tid);
  CP_COMMIT();
  if (tid < 128) fs[tid] = f[ci*128 + tid];
  __syncthreads();
  for (int l = tid; l < 8192; l += 256) {
    int r = l >> 6, c0 = (l & 63) * 2;
    float x0 = (c0 <= r) ? fs[r - c0] : 0.f;
    float x1 = (c0 + 1 <= r) ? fs[r - c0 - 1] : 0.f;
    split_store2(sb, OAH, OAL, r, c0, x0, x1);
  }
  CP_WAIT0();
  __syncthreads();
  float acc[2][8][4] = {};
  gemm3v(sb + OAH, sb + OAL, sb + OBH, sb + OBL, lane, wm, wn, acc);
  float* Cc = g_cs + ((size_t)ch*SEQ + (size_t)ci*128) * NS;
#pragma unroll
  for (int mt = 0; mt < 2; mt++) {
    int r0 = wm*32 + mt*16 + (lane >> 2);
#pragma unroll
    for (int nt = 0; nt < 8; nt++) {
      int gc = wn*64 + nt*8 + 2*(lane & 3);
      *(float2*)(Cc + (size_t)r0*NS + gc)     = make_float2(acc[mt][nt][0], acc[mt][nt][1]);
      *(float2*)(Cc + (size_t)(r0+8)*NS + gc) = make_float2(acc[mt][nt][2], acc[mt][nt][3]);
      if (r0 + 8 == 127)
        *(float2*)(g_U + (size_t)(ch*64 + ci)*NS + gc) = make_float2(acc[mt][nt][2], acc[mt][nt][3]);
    }
  }
}

__global__ __launch_bounds__(256) void k_boundary_h() {
  extern __shared__ char dsm[];
  uint32_t sb = smem_u32(dsm);
  int p = blockIdx.x, rb = blockIdx.y;
  int tid = threadIdx.x, lane = tid & 31, wid = tid >> 5;
  int wm = wid & 3, wn = wid >> 2;
  load_tile(sb + OBH, g_QTth + (size_t)p*NS*NS, 128, tid);
  load_tile(sb + OBL, g_QTtl + (size_t)p*NS*NS, 128, tid);
  CP_COMMIT();
  for (int l = tid; l < 8192; l += 256) {
    int r = l >> 6, c0 = (l & 63) * 2;
    int gr = rb*128 + r;
    bool ok = (gr < 192) && ((gr & 63) >= p);
    float x0 = ok ? g_U[(size_t)(gr - p)*NS + c0] : 0.f;
    float x1 = ok ? g_U[(size_t)(gr - p)*NS + c0 + 1] : 0.f;
    split_store2(sb, OAH, OAL, r, c0, x0, x1);
  }
  CP_WAIT0();
  __syncthreads();
  float acc[2][8][4] = {};
  gemm3v(sb + OAH, sb + OAL, sb + OBH, sb + OBL, lane, wm, wn, acc);
#pragma unroll
  for (int mt = 0; mt < 2; mt++) {
    int r0 = wm*32 + mt*16 + (lane >> 2);
#pragma unroll
    for (int e2 = 0; e2 < 2; e2++) {
      int gr = rb*128 + r0 + e2*8;
      if (gr < 192 && (gr & 63) >= p) {
#pragma unroll
        for (int nt = 0; nt < 8; nt++) {
          int gc = wn*64 + nt*8 + 2*(lane & 3);
          atomicAdd(&g_B[(size_t)gr*NS + gc],     acc[mt][nt][e2*2]);
          atomicAdd(&g_B[(size_t)gr*NS + gc + 1], acc[mt][nt][e2*2 + 1]);
        }
      }
    }
  }
}

__global__ __launch_bounds__(256) void k_propagate_h() {
  extern __shared__ char dsm[];
  uint32_t sb = smem_u32(dsm);
  int r = blockIdx.x, rb = blockIdx.y;
  int tid = threadIdx.x, lane = tid & 31, wid = tid >> 5;
  int wm = wid & 3, wn = wid >> 2;
  load_tile(sb + OBH, g_PTth + (size_t)(r+1)*NS*NS, 128, tid);
  load_tile(sb + OBL, g_PTtl + (size_t)(r+1)*NS*NS, 128, tid);
  CP_COMMIT();
  for (int l = tid; l < 8192; l += 256) {
    int rr = l >> 6, c0 = (l & 63) * 2;
    int gr = rb*128 + rr;
    float x0 = (gr < 192) ? g_B[(size_t)gr*NS + c0] : 0.f;
    float x1 = (gr < 192) ? g_B[(size_t)gr*NS + c0 + 1] : 0.f;
    split_store2(sb, OAH, OAL, rr, c0, x0, x1);
  }
  CP_WAIT0();
  __syncthreads();
  float acc[2][8][4] = {};
  gemm3v(sb + OAH, sb + OAL, sb + OBH, sb + OBL, lane, wm, wn, acc);
#pragma unroll
  for (int mt = 0; mt < 2; mt++) {
    int r0 = wm*32 + mt*16 + (lane >> 2);
#pragma unroll
    for (int e2 = 0; e2 < 2; e2++) {
      int gr = rb*128 + r0 + e2*8;
      if (gr < 192 && (gr & 63) < 63) {
        int ch = gr >> 6, ic = (gr & 63) + 1;
        float* dst = &g_cs[((size_t)ch*SEQ + (size_t)ic*128 + r) * NS];
#pragma unroll
        for (int nt = 0; nt < 8; nt++) {
          int gc = wn*64 + nt*8 + 2*(lane & 3);
          dst[gc]     += acc[mt][nt][e2*2];
          dst[gc + 1] += acc[mt][nt][e2*2 + 1];
        }
      }
    }
  }
}

// ---------------- preps ----------------
__global__ void k_prep_qk() {
  size_t idx = (size_t)blockIdx.x * 256 + threadIdx.x;
  float x = g_cs[idx];
  size_t SN = (size_t)SEQ * NS;
  if (idx < SN) {
    g_qh[idx] = __float2half_rn(x);
  } else {
    __half h = __float2half_rn(x);
    g_kh[idx - SN] = h;
    g_kl[idx - SN] = __float2half_rn(x - __half2float(h));
  }
}
__global__ void k_prep_vt() {
  __shared__ float t[32][33];
  int t0 = blockIdx.x * 32, n0 = blockIdx.y * 32;
  int tx = threadIdx.x, ty = threadIdx.y;
  const float* v = g_cs + (size_t)2 * SEQ * NS;
#pragma unroll
  for (int j = 0; j < 32; j += 8) t[ty+j][tx] = v[(size_t)(t0 + ty + j)*NS + n0 + tx];
  __syncthreads();
#pragma unroll
  for (int j = 0; j < 32; j += 8) {
    float x = t[tx][ty+j];
    __half h = __float2half_rn(x);
    __half l = __float2half_rn(x - __half2float(h));
    size_t o = (size_t)(n0 + ty + j) * SEQ + t0 + tx;
    g_vth[o] = h; g_vtl[o] = l;
  }
}
__global__ void k_prep_wpt(const float* __restrict__ Wp) {
  __shared__ float t[32][33];
  int n0 = blockIdx.x * 32, k0 = blockIdx.y * 32;
  int tx = threadIdx.x, ty = threadIdx.y;
#pragma unroll
  for (int j = 0; j < 32; j += 8) {
    int n = n0 + tx;
    t[ty+j][tx] = (n < OUTD) ? Wp[(size_t)(k0 + ty + j)*OUTD + n] : 0.f;
  }
  __syncthreads();
#pragma unroll
  for (int j = 0; j < 32; j += 8) {
    __nv_bfloat16 h, l;
    split16(t[tx][ty+j], h, l);
    size_t o = (size_t)(n0 + ty + j) * NS + k0 + tx;
    g_wph[o] = h; g_wpl[o] = l;
  }
}

// ---------------- QK^T (fp16 2-pass) + fused stats ----------------
__device__ __forceinline__ void qk_epilogue(float* __restrict__ S, int ib, int jb,
                                            int wm, int wn, int lane, float acc[2][8][4]) {
#pragma unroll
  for (int mt = 0; mt < 2; mt++)
#pragma unroll
    for (int nt = 0; nt < 8; nt++)
#pragma unroll
      for (int e = 0; e < 4; e++) acc[mt][nt][e] *= 0.25f;
  int jc = jb * 2 + wn;
#pragma unroll
  for (int mt = 0; mt < 2; mt++) {
    int r0 = ib*128 + wm*32 + mt*16 + (lane >> 2);
    float mx0 = -3.4e38f, mx1 = -3.4e38f;
#pragma unroll
    for (int nt = 0; nt < 8; nt++) {
      mx0 = fmaxf(mx0, fmaxf(acc[mt][nt][0], acc[mt][nt][1]));
      mx1 = fmaxf(mx1, fmaxf(acc[mt][nt][2], acc[mt][nt][3]));
    }
    mx0 = fmaxf(mx0, __shfl_xor_sync(~0u, mx0, 1));
    mx0 = fmaxf(mx0, __shfl_xor_sync(~0u, mx0, 2));
    mx1 = fmaxf(mx1, __shfl_xor_sync(~0u, mx1, 1));
    mx1 = fmaxf(mx1, __shfl_xor_sync(~0u, mx1, 2));
    float s0 = 0.f, s1 = 0.f;
#pragma unroll
    for (int nt = 0; nt < 8; nt++) {
      s0 += __expf(acc[mt][nt][0] - mx0) + __expf(acc[mt][nt][1] - mx0);
      s1 += __expf(acc[mt][nt][2] - mx1) + __expf(acc[mt][nt][3] - mx1);
    }
    s0 += __shfl_xor_sync(~0u, s0, 1); s0 += __shfl_xor_sync(~0u, s0, 2);
    s1 += __shfl_xor_sync(~0u, s1, 1); s1 += __shfl_xor_sync(~0u, s1, 2);
    if ((lane & 3) == 0) {
      g_tmax[(size_t)jc*SEQ + r0] = mx0;     g_tsum[(size_t)jc*SEQ + r0] = s0;
      g_tmax[(size_t)jc*SEQ + r0 + 8] = mx1; g_tsum[(size_t)jc*SEQ + r0 + 8] = s1;
    }
    int colb = jb*128 + wn*64 + 2*(lane & 3);
#pragma unroll
    for (int nt = 0; nt < 8; nt++) {
      *(float2*)(S + (size_t)r0*SEQ + colb + nt*8)     = make_float2(acc[mt][nt][0], acc[mt][nt][1]);
      *(float2*)(S + (size_t)(r0+8)*SEQ + colb + nt*8) = make_float2(acc[mt][nt][2], acc[mt][nt][3]);
    }
  }
}

__global__ __launch_bounds__(256) void k_qk_mma(float* __restrict__ S) {
  extern __shared__ char dsm[];
  uint32_t sb = smem_u32(dsm);
  int tid = threadIdx.x, lane = tid & 31, wid = tid >> 5;
  int wm = wid & 3, wn = wid >> 2;
  int ib = blockIdx.x, jb0 = blockIdx.y * 2, jb1 = jb0 + 1;

  load_tile(sb + QKA,   g_qh + (size_t)ib*128*NS, NS, tid);
  load_tile(sb + QKB0H, g_kh + (size_t)jb0*128*NS, NS, tid);
  load_tile(sb + QKB0L, g_kl + (size_t)jb0*128*NS, NS, tid);
  CP_COMMIT();
  load_tile(sb + QKB1H, g_kh + (size_t)jb1*128*NS, NS, tid);
  load_tile(sb + QKB1L, g_kl + (size_t)jb1*128*NS, NS, tid);
  CP_COMMIT();
  CP_WAIT1();
  __syncthreads();
  {
    float acc[2][8][4] = {};
    gemm_pass_h(sb + QKA, sb + QKB0H, lane, wm, wn, acc);
    gemm_pass_h(sb + QKA, sb + QKB0L, lane, wm, wn, acc);
    qk_epilogue(S, ib, jb0, wm, wn, lane, acc);
  }
  CP_WAIT0();
  __syncthreads();
  {
    float acc[2][8][4] = {};
    gemm_pass_h(sb + QKA, sb + QKB1H, lane, wm, wn, acc);
    gemm_pass_h(sb + QKA, sb + QKB1L, lane, wm, wn, acc);
    qk_epilogue(S, ib, jb1, wm, wn, lane, acc);
  }
}

__global__ void k_combine() {
  int row = blockIdx.x * 256 + threadIdx.x;
  float mx = -3.4e38f;
  for (int j = 0; j < 128; j++) mx = fmaxf(mx, g_tmax[(size_t)j*SEQ + row]);
  float s = 0.f;
  for (int j = 0; j < 128; j++) s += g_tsum[(size_t)j*SEQ + row] * __expf(g_tmax[(size_t)j*SEQ + row] - mx);
  g_RM[row] = mx;
  g_RSI[row] = 1.0f / s;
}

// ---------------- softmax + attn write + attn@V (fp16 2-pass, double-buffered V) ----------------
__global__ __launch_bounds__(256) void k_ctx_mma(float* __restrict__ S) {
  extern __shared__ char dsm[];
  uint32_t sb = smem_u32(dsm);
  int tid = threadIdx.x, lane = tid & 31, wid = tid >> 5;
  int wm = wid & 3, wn = wid >> 2;
  int ib = blockIdx.x, sp = blockIdx.y;

  int crow = tid >> 1;
  int cbase = (tid & 1) * 64;
  float m = g_RM[ib*128 + crow];
  float li = g_RSI[ib*128 + crow];

  load_tile(sb + CVH0, g_vth + sp*1024, SEQ, tid);
  load_tile(sb + CVL0, g_vtl + sp*1024, SEQ, tid);
  CP_COMMIT();

  float acc[2][8][4] = {};
  for (int c = 0; c < 8; c++) {
    uint32_t bH = (c & 1) ? CVH1 : CVH0;
    uint32_t bL = (c & 1) ? CVL1 : CVL0;
    if (c < 7) {
      uint32_t nH = (c & 1) ? CVH0 : CVH1;
      uint32_t nL = (c & 1) ? CVL0 : CVL1;
      int kn = sp*1024 + (c+1)*128;
      load_tile(sb + nH, g_vth + kn, SEQ, tid);
      load_tile(sb + nL, g_vtl + kn, SEQ, tid);
      CP_COMMIT();
    }
    int k0 = sp*1024 + c*128;
    float2* srow = (float2*)(S + (size_t)(ib*128 + crow)*SEQ + k0 + cbase);
    uint32_t abase = sb + CTA_A + (uint32_t)((crow * TPAD + cbase) << 1);
#pragma unroll 8
    for (int i = 0; i < 32; i++) {
      float2 s2 = srow[i];
      float a0 = __expf(s2.x - m) * li;
      float a1 = __expf(s2.y - m) * li;
      srow[i] = make_float2(a0, a1);
      sts32(abase + i*4, packh(__float2half_rn(a0), __float2half_rn(a1)));
    }
    if (c < 7) CP_WAIT1(); else CP_WAIT0();
    __syncthreads();
    gemm_pass_h(sb + CTA_A, sb + bH, lane, wm, wn, acc);
    gemm_pass_h(sb + CTA_A, sb + bL, lane, wm, wn, acc);
    __syncthreads();
  }
#pragma unroll
  for (int mt = 0; mt < 2; mt++) {
    int r0 = ib*128 + wm*32 + mt*16 + (lane >> 2);
    int colb = wn*64 + 2*(lane & 3);
#pragma unroll
    for (int nt = 0; nt < 8; nt++) {
      *(float2*)(g_ctxp + ((size_t)sp*SEQ + r0)*NS + colb + nt*8)     = make_float2(acc[mt][nt][0], acc[mt][nt][1]);
      *(float2*)(g_ctxp + ((size_t)sp*SEQ + r0 + 8)*NS + colb + nt*8) = make_float2(acc[mt][nt][2], acc[mt][nt][3]);
    }
  }
}

__global__ void k_ctxred() {
  size_t idx = (size_t)blockIdx.x * 256 + threadIdx.x;
  float acc = 0.f;
#pragma unroll
  for (int s = 0; s < 8; s++) acc += g_ctxp[(size_t)s*SEQ*NS + idx];
  __nv_bfloat16 h, l;
  split16(acc, h, l);
  g_ch[idx] = h; g_clo[idx] = l;
}

// ---------------- out = ctx @ Wp + bp (bf16 3-pass) ----------------
__global__ __launch_bounds__(256) void k_out_mma(float* __restrict__ out, const float* __restrict__ bp) {
  extern __shared__ char dsm[];
  uint32_t sb = smem_u32(dsm);
  int tid = threadIdx.x, lane = tid & 31, wid = tid >> 5;
  int wm = wid & 3, wn = wid >> 2;
  int ib = blockIdx.x, cb = blockIdx.y;

  load_tile(sb + OAH, g_ch  + (size_t)ib*128*NS, NS, tid);
  load_tile(sb + OAL, g_clo + (size_t)ib*128*NS, NS, tid);
  load_tile(sb + OBH, g_wph + (size_t)cb*128*NS, NS, tid);
  load_tile(sb + OBL, g_wpl + (size_t)cb*128*NS, NS, tid);
  CP_COMMIT(); CP_WAIT0();
  __syncthreads();

  float acc[2][8][4] = {};
  gemm3v(sb + OAH, sb + OAL, sb + OBH, sb + OBL, lane, wm, wn, acc);

#pragma unroll
  for (int mt = 0; mt < 2; mt++) {
    int r0 = ib*128 + wm*32 + mt*16 + (lane >> 2);
#pragma unroll
    for (int nt = 0; nt < 8; nt++) {
      int gc = cb*128 + wn*64 + nt*8 + 2*(lane & 3);
      if (gc + 1 < OUTD) {
        out[(size_t)r0*OUTD + gc]         = acc[mt][nt][0] + bp[gc];
        out[(size_t)r0*OUTD + gc + 1]     = acc[mt][nt][1] + bp[gc + 1];
        out[(size_t)(r0+8)*OUTD + gc]     = acc[mt][nt][2] + bp[gc];
        out[(size_t)(r0+8)*OUTD + gc + 1] = acc[mt][nt][3] + bp[gc + 1];
      } else if (gc < OUTD) {
        out[(size_t)r0*OUTD + gc]     = acc[mt][nt][0] + bp[gc];
        out[(size_t)(r0+8)*OUTD + gc] = acc[mt][nt][2] + bp[gc];
      }
    }
  }
}

// ---------------- launch ----------------
extern "C" void kernel_launch(void* const* d_in, const int* in_sizes, int n_in,
                              void* d_out, int out_size) {
  const float* q  = (const float*)d_in[0];
  const float* kk = (const float*)d_in[1];
  const float* vv = (const float*)d_in[2];
  const float* GA = (const float*)d_in[3];
  const float* GB = (const float*)d_in[4];
  const float* Wp = (const float*)d_in[5];
  const float* bp = (const float*)d_in[6];
  float* out = (float*)d_out;

  cudaFuncSetAttribute(k_powers_f,    cudaFuncAttributeMaxDynamicSharedMemorySize, POW_SM);
  cudaFuncSetAttribute(k_localconv_h, cudaFuncAttributeMaxDynamicSharedMemorySize, SCAN2_SM);
  cudaFuncSetAttribute(k_boundary_h,  cudaFuncAttributeMaxDynamicSharedMemorySize, SCAN2_SM);
  cudaFuncSetAttribute(k_propagate_h, cudaFuncAttributeMaxDynamicSharedMemorySize, SCAN2_SM);
  cudaFuncSetAttribute(k_qk_mma,      cudaFuncAttributeMaxDynamicSharedMemorySize, QK_SM);
  cudaFuncSetAttribute(k_ctx_mma,     cudaFuncAttributeMaxDynamicSharedMemorySize, CTX_SM);
  cudaFuncSetAttribute(k_out_mma,     cudaFuncAttributeMaxDynamicSharedMemorySize, GEMM_SM);

  float* pFB;
  cudaGetSymbolAddress((void**)&pFB, g_attn_fb);
  float* S = (out_size >= (int)((size_t)SEQ*OUTD + (size_t)SEQ*SEQ)) ? out + (size_t)SEQ*OUTD : pFB;

  k_prep_wpt<<<dim3(32, 4), dim3(32, 8)>>>(Wp);          // 0
  k_init<<<128, 128>>>(GA);                              // 1
  k_prep_small<<<1, 256>>>(GB);                          // 2
  k_powers_f<<<191, 256, POW_SM>>>(GB);                  // 3 ← ncu profiled slot
  k_localconv_h<<<dim3(64, 3), 256, SCAN2_SM>>>(q, kk, vv);
  k_boundary_h<<<dim3(64, 2), 256, SCAN2_SM>>>();
  k_propagate_h<<<dim3(128, 2), 256, SCAN2_SM>>>();
  k_prep_qk<<<8192, 256>>>();
  k_prep_vt<<<dim3(256, 4), dim3(32, 8)>>>();
  k_qk_mma<<<dim3(64, 32), 256, QK_SM>>>(S);
  k_combine<<<32, 256>>>();
  k_ctx_mma<<<dim3(64, 8), 256, CTX_SM>>>(S);
  k_ctxred<<<4096, 256>>>();
  k_out_mma<<<dim3(64, 8), 256, GEMM_SM>>>(out, bp);
}

// round 16
// speedup vs baseline: 1.2922x; 1.0824x over previous
#include <cuda_runtime.h>
#include <cuda_bf16.h>
#include <cuda_fp16.h>
#include <math.h>
#include <stdint.h>
typedef unsigned long long ull;

#define NS   128
#define SEQ  8192
#define OUTD 1000

// ---------------- device scratch ----------------
__device__ float g_PT[(size_t)2 * NS * NS];
__device__ float g_cs[(size_t)3 * SEQ * NS];
__device__ float g_U[3 * 64 * NS];
__device__ float g_B[3 * 64 * NS];
__device__ float g_ctxp[(size_t)8 * SEQ * NS];
__device__ float g_attn_fb[(size_t)SEQ * SEQ];
__device__ float g_tmax[(size_t)128 * SEQ];
__device__ float g_tsum[(size_t)128 * SEQ];
__device__ float g_RM[SEQ];
__device__ float g_RSI[SEQ];
// fp16 q,k (hi only) for 1-pass qk
__device__ __align__(256) __half g_qh[(size_t)SEQ * NS];
__device__ __align__(256) __half g_kh[(size_t)SEQ * NS];
// fp16 V hi/lo for 2-pass ctx
__device__ __align__(256) __half g_vth[(size_t)NS * SEQ], g_vtl[(size_t)NS * SEQ];
// bf16 for out (3-pass)
__device__ __align__(256) __nv_bfloat16 g_ch[(size_t)SEQ * NS], g_clo[(size_t)SEQ * NS];
__device__ __align__(256) __nv_bfloat16 g_wph[(size_t)1024 * NS], g_wpl[(size_t)1024 * NS];
__device__ __align__(256) __nv_bfloat16 g_PTth[(size_t)129 * NS * NS], g_PTtl[(size_t)129 * NS * NS];
__device__ __align__(256) __nv_bfloat16 g_QTth[(size_t)64 * NS * NS],  g_QTtl[(size_t)64 * NS * NS];
__device__ __align__(256) __nv_bfloat16 g_Kth[NS * NS], g_Ktl[NS * NS];

// ---------------- PTX helpers ----------------
__device__ __forceinline__ uint32_t smem_u32(const void* p) {
  uint32_t a;
  asm("{ .reg .u64 t; cvta.to.shared.u64 t, %1; cvt.u32.u64 %0, t; }" : "=r"(a) : "l"(p));
  return a;
}
__device__ __forceinline__ void cp16(uint32_t d, const void* s) {
  asm volatile("cp.async.cg.shared.global [%0], [%1], 16;" ::"r"(d),"l"(s):"memory");
}
#define CP_COMMIT() asm volatile("cp.async.commit_group;" :::"memory")
#define CP_WAIT0()  asm volatile("cp.async.wait_group 0;" :::"memory")
#define CP_WAIT1()  asm volatile("cp.async.wait_group 1;" :::"memory")
__device__ __forceinline__ void sts32(uint32_t a, uint32_t v) {
  asm volatile("st.shared.b32 [%0], %1;" ::"r"(a),"r"(v):"memory");
}
__device__ __forceinline__ void ldm4(uint32_t a, uint32_t f[4]) {
  asm volatile("ldmatrix.sync.aligned.m8n8.x4.shared.b16 {%0,%1,%2,%3}, [%4];"
    : "=r"(f[0]),"=r"(f[1]),"=r"(f[2]),"=r"(f[3]) : "r"(a));
}
__device__ __forceinline__ void mma16816(float c[4], const uint32_t a[4], const uint32_t b0, const uint32_t b1) {
  asm volatile("mma.sync.aligned.m16n8k16.row.col.f32.bf16.bf16.f32 "
    "{%0,%1,%2,%3},{%4,%5,%6,%7},{%8,%9},{%0,%1,%2,%3};"
    : "+f"(c[0]),"+f"(c[1]),"+f"(c[2]),"+f"(c[3])
    : "r"(a[0]),"r"(a[1]),"r"(a[2]),"r"(a[3]),"r"(b0),"r"(b1));
}
__device__ __forceinline__ void mma16816h(float c[4], const uint32_t a[4], const uint32_t b0, const uint32_t b1) {
  asm volatile("mma.sync.aligned.m16n8k16.row.col.f32.f16.f16.f32 "
    "{%0,%1,%2,%3},{%4,%5,%6,%7},{%8,%9},{%0,%1,%2,%3};"
    : "+f"(c[0]),"+f"(c[1]),"+f"(c[2]),"+f"(c[3])
    : "r"(a[0]),"r"(a[1]),"r"(a[2]),"r"(a[3]),"r"(b0),"r"(b1));
}

// padded 16-bit tile: 128 rows x 136 cols
#define TPAD 136
#define TILE_B (128 * TPAD * 2)
#define OAH 0u
#define OAL (1u * TILE_B)
#define OBH (2u * TILE_B)
#define OBL (3u * TILE_B)
#define GEMM_SM  (4 * TILE_B)
// qk layout (1-pass): A=qh + kh(jb0) + kh(jb1) = 3 tiles
#define QKA  0u
#define QKB0 (1u * TILE_B)
#define QKB1 (2u * TILE_B)
#define QK_SM (3 * TILE_B)
// ctx layout: A(attn fp16 hi) + V hi/lo double-buffered = 5 tiles
#define CTA_A 0u
#define CVH0 (1u * TILE_B)
#define CVL0 (2u * TILE_B)
#define CVH1 (3u * TILE_B)
#define CVL1 (4u * TILE_B)
#define CTX_SM (5 * TILE_B)
#define SCAN2_SM (4 * TILE_B + 512)
#define POW_SM   (2 * 128 * 132 * 4)

// 256-thread tile loader (element size 2B)
__device__ __forceinline__ void load_tile(uint32_t sbt, const void* src_, int stride, int tid) {
  const __half* src = (const __half*)src_;
#pragma unroll
  for (int t = tid; t < 2048; t += 256) {
    int row = t >> 4, col = (t & 15) << 3;
    cp16(sbt + row * (TPAD * 2) + (col << 1), src + (size_t)row * stride + col);
  }
}

// pipelined 8-warp gemm pass (bf16): warp = 32m x 64n
__device__ __forceinline__ void gemm_pass(uint32_t sA, uint32_t sB, int lane, int wm, int wn,
                                          float acc[2][8][4]) {
  uint32_t aB0 = sA + (uint32_t)(((wm*32 + (lane & 15)) * TPAD + ((lane >> 4) << 3)) << 1);
  uint32_t aB1 = aB0 + (uint32_t)((16 * TPAD) << 1);
  uint32_t bB[4];
#pragma unroll
  for (int np = 0; np < 4; np++)
    bB[np] = sB + (uint32_t)(((wn*64 + np*16 + (lane & 7) + ((lane >> 4) << 3)) * TPAD + (lane & 8)) << 1);
  uint32_t afr[2][2][4];
  uint32_t bfr[2][4][4];
  ldm4(aB0, afr[0][0]);
  ldm4(aB1, afr[0][1]);
#pragma unroll
  for (int np = 0; np < 4; np++) ldm4(bB[np], bfr[0][np]);
#pragma unroll
  for (int ks = 0; ks < 8; ks++) {
    int cur = ks & 1, nxt = cur ^ 1;
    if (ks < 7) {
      uint32_t off = (uint32_t)((ks + 1) * 32);
      ldm4(aB0 + off, afr[nxt][0]);
      ldm4(aB1 + off, afr[nxt][1]);
#pragma unroll
      for (int np = 0; np < 4; np++) ldm4(bB[np] + off, bfr[nxt][np]);
    }
#pragma unroll
    for (int np = 0; np < 4; np++) {
#pragma unroll
      for (int mt = 0; mt < 2; mt++) {
        mma16816(acc[mt][np * 2],     afr[cur][mt], bfr[cur][np][0], bfr[cur][np][1]);
        mma16816(acc[mt][np * 2 + 1], afr[cur][mt], bfr[cur][np][2], bfr[cur][np][3]);
      }
    }
  }
}
// fp16 variant
__device__ __forceinline__ void gemm_pass_h(uint32_t sA, uint32_t sB, int lane, int wm, int wn,
                                            float acc[2][8][4]) {
  uint32_t aB0 = sA + (uint32_t)(((wm*32 + (lane & 15)) * TPAD + ((lane >> 4) << 3)) << 1);
  uint32_t aB1 = aB0 + (uint32_t)((16 * TPAD) << 1);
  uint32_t bB[4];
#pragma unroll
  for (int np = 0; np < 4; np++)
    bB[np] = sB + (uint32_t)(((wn*64 + np*16 + (lane & 7) + ((lane >> 4) << 3)) * TPAD + (lane & 8)) << 1);
  uint32_t afr[2][2][4];
  uint32_t bfr[2][4][4];
  ldm4(aB0, afr[0][0]);
  ldm4(aB1, afr[0][1]);
#pragma unroll
  for (int np = 0; np < 4; np++) ldm4(bB[np], bfr[0][np]);
#pragma unroll
  for (int ks = 0; ks < 8; ks++) {
    int cur = ks & 1, nxt = cur ^ 1;
    if (ks < 7) {
      uint32_t off = (uint32_t)((ks + 1) * 32);
      ldm4(aB0 + off, afr[nxt][0]);
      ldm4(aB1 + off, afr[nxt][1]);
#pragma unroll
      for (int np = 0; np < 4; np++) ldm4(bB[np] + off, bfr[nxt][np]);
    }
#pragma unroll
    for (int np = 0; np < 4; np++) {
#pragma unroll
      for (int mt = 0; mt < 2; mt++) {
        mma16816h(acc[mt][np * 2],     afr[cur][mt], bfr[cur][np][0], bfr[cur][np][1]);
        mma16816h(acc[mt][np * 2 + 1], afr[cur][mt], bfr[cur][np][2], bfr[cur][np][3]);
      }
    }
  }
}
__device__ __forceinline__ void gemm3v(uint32_t aH, uint32_t aL, uint32_t bH, uint32_t bL,
                                       int lane, int wm, int wn, float acc[2][8][4]) {
  gemm_pass(aH, bH, lane, wm, wn, acc);
  gemm_pass(aH, bL, lane, wm, wn, acc);
  gemm_pass(aL, bH, lane, wm, wn, acc);
}

__device__ __forceinline__ void split16(float x, __nv_bfloat16& h, __nv_bfloat16& l) {
  h = __float2bfloat16(x);
  l = __float2bfloat16(x - __bfloat162float(h));
}
__device__ __forceinline__ uint32_t packbf(__nv_bfloat16 lo_e, __nv_bfloat16 hi_e) {
  return ((uint32_t)__bfloat16_as_ushort(hi_e) << 16) | __bfloat16_as_ushort(lo_e);
}
__device__ __forceinline__ uint32_t packh(__half lo_e, __half hi_e) {
  return ((uint32_t)__half_as_ushort(hi_e) << 16) | __half_as_ushort(lo_e);
}
__device__ __forceinline__ void split_store2(uint32_t sb, uint32_t offH, uint32_t offL,
                                             int r, int c0, float x0, float x1) {
  __nv_bfloat16 h0, l0, h1, l1;
  split16(x0, h0, l0); split16(x1, h1, l1);
  uint32_t off = (uint32_t)(r * TPAD + c0) << 1;
  sts32(sb + offH + off, packbf(h0, h1));
  sts32(sb + offL + off, packbf(l0, l1));
}

// ---------------- f32x2 mm (k_powers only — R14-measured-fastest form) ----------------
__device__ __forceinline__ float2 upk(ull p) {
  float2 r; asm("mov.b64 {%0,%1}, %2;" : "=f"(r.x), "=f"(r.y) : "l"(p)); return r;
}
__device__ __forceinline__ void mm128(const float* As, const float* Bs, int tx, int ty, ull acc[8][4]) {
#pragma unroll 4
  for (int kk = 0; kk < 128; kk++) {
    ull bp[4];
#pragma unroll
    for (int j = 0; j < 4; j++) bp[j] = *(const ull*)&Bs[kk*132 + tx*8 + j*2];
#pragma unroll
    for (int i = 0; i < 8; i++) {
      float a = As[(ty*8+i)*132 + kk];
      ull ap; asm("mov.b64 %0,{%1,%1};" : "=l"(ap) : "f"(a));
#pragma unroll
      for (int j = 0; j < 4; j++)
        asm("fma.rn.f32x2 %0,%1,%2,%0;" : "+l"(acc[i][j]) : "l"(ap), "l"(bp[j]));
    }
  }
}

__global__ void k_init(const float* __restrict__ GA) {
  int m = blockIdx.x, n = threadIdx.x;
  g_PT[m*NS+n] = (m==n) ? 1.f : 0.f;
  g_PT[NS*NS + m*NS + n] = GA[n*NS + m];
}

// QTth[0]=I; Kth col 0 = split(GB); zero g_B
__global__ void k_prep_small(const float* __restrict__ GB) {
  int tid = threadIdx.x;
  __nv_bfloat16 one = __float2bfloat16(1.f), zero = __float2bfloat16(0.f);
  for (int l = tid; l < 8192; l += 256) {
    int n = l >> 6, k0 = (l & 63) * 2;
    uint32_t h = 0;
    if (n == k0) h = packbf(one, zero);
    else if (n == k0 + 1) h = packbf(zero, one);
    *(uint32_t*)(g_QTth + n*128 + k0) = h;
    *(uint32_t*)(g_QTtl + n*128 + k0) = 0;
  }
  if (tid < 128) {
    __nv_bfloat16 h, l;
    split16(GB[tid], h, l);
    g_Kth[tid*128 + 0] = h;
    g_Ktl[tid*128 + 0] = l;
  }
  for (int i = tid; i < 3*64*NS; i += 256) g_B[i] = 0.f;
}

__global__ __launch_bounds__(256) void k_powers_f(const float* __restrict__ GB) {
  extern __shared__ float sm[];
  float* R = sm;
  float* G = sm + 128*132;
  int b = blockIdx.x, tid = threadIdx.x, tx = tid & 15, ty = tid >> 4;
  int e; __nv_bfloat16 *dh, *dl;
  if (b < 128) { e = b + 1; dh = g_PTth + (size_t)(b+1)*NS*NS; dl = g_PTtl + (size_t)(b+1)*NS*NS; }
  else { int p = b - 127; e = p << 7; dh = g_QTth + (size_t)p*NS*NS; dl = g_QTtl + (size_t)p*NS*NS; }
  const float* GAT = g_PT + NS*NS;
  for (int l = tid; l < NS*NS; l += 256) {
    int r = l >> 7, c = l & 127;
    float v = GAT[l];
    G[r*132+c] = v; R[r*132+c] = v;
  }
  __syncthreads();
  int msb = 31 - __clz(e);
  for (int bit = msb - 1; bit >= 0; bit--) {
    {
      ull acc[8][4] = {};
      mm128(R, R, tx, ty, acc);
      __syncthreads();
#pragma unroll
      for (int i = 0; i < 8; i++)
#pragma unroll
        for (int j = 0; j < 4; j++) {
          float2 v = upk(acc[i][j]);
          R[(ty*8+i)*132 + tx*8 + j*2] = v.x;
          R[(ty*8+i)*132 + tx*8 + j*2 + 1] = v.y;
        }
      __syncthreads();
    }
    if ((e >> bit) & 1) {
      ull acc[8][4] = {};
      mm128(R, G, tx, ty, acc);
      __syncthreads();
#pragma unroll
      for (int i = 0; i < 8; i++)
#pragma unroll
        for (int j = 0; j < 4; j++) {
          float2 v = upk(acc[i][j]);
          R[(ty*8+i)*132 + tx*8 + j*2] = v.x;
          R[(ty*8+i)*132 + tx*8 + j*2 + 1] = v.y;
        }
      __syncthreads();
    }
  }
  for (int l = tid; l < 8192; l += 256) {
    int n = l >> 6, k0 = (l & 63) * 2;
    __nv_bfloat16 h0, l0, h1, l1;
    split16(R[k0*132 + n], h0, l0);
    split16(R[(k0+1)*132 + n], h1, l1);
    *(uint32_t*)(dh + (size_t)n*128 + k0) = packbf(h0, h1);
    *(uint32_t*)(dl + (size_t)n*128 + k0) = packbf(l0, l1);
  }
  if (b < 127 && tid < 128) {
    int n = tid;
    float acc = 0.f;
#pragma unroll 4
    for (int m = 0; m < 128; m++) acc = fmaf(R[m*132 + n], GB[m], acc);
    __nv_bfloat16 h, l;
    split16(acc, h, l);
    g_Kth[n*128 + (b+1)] = h;
    g_Ktl[n*128 + (b+1)] = l;
  }
}

// ---------------- scan GEMMs (bf16 3-pass) ----------------
__global__ __launch_bounds__(256) void k_localconv_h(const float* __restrict__ fq,
                                                     const float* __restrict__ fk,
                                                     const float* __restrict__ fv) {
  extern __shared__ char dsm[];
  uint32_t sb = smem_u32(dsm);
  float* fs = (float*)(dsm + 4*TILE_B);
  int ci = blockIdx.x, ch = blockIdx.y;
  const float* f = (ch == 0) ? fq : ((ch == 1) ? fk : fv);
  int tid = threadIdx.x, lane = tid & 31, wid = tid >> 5;
  int wm = wid & 3, wn = wid >> 2;
  load_tile(sb + OBH, g_Kth, 128, tid);
  load_tile(sb + OBL, g_Ktl, 128, tid);
  CP_COMMIT();
  if (tid < 128) fs[tid] = f[ci*128 + tid];
  __syncthreads();
  for (int l = tid; l < 8192; l += 256) {
    int r = l >> 6, c0 = (l & 63) * 2;
    float x0 = (c0 <= r) ? fs[r - c0] : 0.f;
    float x1 = (c0 + 1 <= r) ? fs[r - c0 - 1] : 0.f;
    split_store2(sb, OAH, OAL, r, c0, x0, x1);
  }
  CP_WAIT0();
  __syncthreads();
  float acc[2][8][4] = {};
  gemm3v(sb + OAH, sb + OAL, sb + OBH, sb + OBL, lane, wm, wn, acc);
  float* Cc = g_cs + ((size_t)ch*SEQ + (size_t)ci*128) * NS;
#pragma unroll
  for (int mt = 0; mt < 2; mt++) {
    int r0 = wm*32 + mt*16 + (lane >> 2);
#pragma unroll
    for (int nt = 0; nt < 8; nt++) {
      int gc = wn*64 + nt*8 + 2*(lane & 3);
      *(float2*)(Cc + (size_t)r0*NS + gc)     = make_float2(acc[mt][nt][0], acc[mt][nt][1]);
      *(float2*)(Cc + (size_t)(r0+8)*NS + gc) = make_float2(acc[mt][nt][2], acc[mt][nt][3]);
      if (r0 + 8 == 127)
        *(float2*)(g_U + (size_t)(ch*64 + ci)*NS + gc) = make_float2(acc[mt][nt][2], acc[mt][nt][3]);
    }
  }
}

__global__ __launch_bounds__(256) void k_boundary_h() {
  extern __shared__ char dsm[];
  uint32_t sb = smem_u32(dsm);
  int p = blockIdx.x, rb = blockIdx.y;
  int tid = threadIdx.x, lane = tid & 31, wid = tid >> 5;
  int wm = wid & 3, wn = wid >> 2;
  load_tile(sb + OBH, g_QTth + (size_t)p*NS*NS, 128, tid);
  load_tile(sb + OBL, g_QTtl + (size_t)p*NS*NS, 128, tid);
  CP_COMMIT();
  for (int l = tid; l < 8192; l += 256) {
    int r = l >> 6, c0 = (l & 63) * 2;
    int gr = rb*128 + r;
    bool ok = (gr < 192) && ((gr & 63) >= p);
    float x0 = ok ? g_U[(size_t)(gr - p)*NS + c0] : 0.f;
    float x1 = ok ? g_U[(size_t)(gr - p)*NS + c0 + 1] : 0.f;
    split_store2(sb, OAH, OAL, r, c0, x0, x1);
  }
  CP_WAIT0();
  __syncthreads();
  float acc[2][8][4] = {};
  gemm3v(sb + OAH, sb + OAL, sb + OBH, sb + OBL, lane, wm, wn, acc);
#pragma unroll
  for (int mt = 0; mt < 2; mt++) {
    int r0 = wm*32 + mt*16 + (lane >> 2);
#pragma unroll
    for (int e2 = 0; e2 < 2; e2++) {
      int gr = rb*128 + r0 + e2*8;
      if (gr < 192 && (gr & 63) >= p) {
#pragma unroll
        for (int nt = 0; nt < 8; nt++) {
          int gc = wn*64 + nt*8 + 2*(lane & 3);
          atomicAdd(&g_B[(size_t)gr*NS + gc],     acc[mt][nt][e2*2]);
          atomicAdd(&g_B[(size_t)gr*NS + gc + 1], acc[mt][nt][e2*2 + 1]);
        }
      }
    }
  }
}

__global__ __launch_bounds__(256) void k_propagate_h() {
  extern __shared__ char dsm[];
  uint32_t sb = smem_u32(dsm);
  int r = blockIdx.x, rb = blockIdx.y;
  int tid = threadIdx.x, lane = tid & 31, wid = tid >> 5;
  int wm = wid & 3, wn = wid >> 2;
  load_tile(sb + OBH, g_PTth + (size_t)(r+1)*NS*NS, 128, tid);
  load_tile(sb + OBL, g_PTtl + (size_t)(r+1)*NS*NS, 128, tid);
  CP_COMMIT();
  for (int l = tid; l < 8192; l += 256) {
    int rr = l >> 6, c0 = (l & 63) * 2;
    int gr = rb*128 + rr;
    float x0 = (gr < 192) ? g_B[(size_t)gr*NS + c0] : 0.f;
    float x1 = (gr < 192) ? g_B[(size_t)gr*NS + c0 + 1] : 0.f;
    split_store2(sb, OAH, OAL, rr, c0, x0, x1);
  }
  CP_WAIT0();
  __syncthreads();
  float acc[2][8][4] = {};
  gemm3v(sb + OAH, sb + OAL, sb + OBH, sb + OBL, lane, wm, wn, acc);
#pragma unroll
  for (int mt = 0; mt < 2; mt++) {
    int r0 = wm*32 + mt*16 + (lane >> 2);
#pragma unroll
    for (int e2 = 0; e2 < 2; e2++) {
      int gr = rb*128 + r0 + e2*8;
      if (gr < 192 && (gr & 63) < 63) {
        int ch = gr >> 6, ic = (gr & 63) + 1;
        float* dst = &g_cs[((size_t)ch*SEQ + (size_t)ic*128 + r) * NS];
#pragma unroll
        for (int nt = 0; nt < 8; nt++) {
          int gc = wn*64 + nt*8 + 2*(lane & 3);
          dst[gc]     += acc[mt][nt][e2*2];
          dst[gc + 1] += acc[mt][nt][e2*2 + 1];
        }
      }
    }
  }
}

// ---------------- preps ----------------
__global__ void k_prep_qk() {
  size_t idx = (size_t)blockIdx.x * 256 + threadIdx.x;
  float x = g_cs[idx];
  size_t SN = (size_t)SEQ * NS;
  if (idx < SN) g_qh[idx] = __float2half_rn(x);
  else          g_kh[idx - SN] = __float2half_rn(x);
}
__global__ void k_prep_vt() {
  __shared__ float t[32][33];
  int t0 = blockIdx.x * 32, n0 = blockIdx.y * 32;
  int tx = threadIdx.x, ty = threadIdx.y;
  const float* v = g_cs + (size_t)2 * SEQ * NS;
#pragma unroll
  for (int j = 0; j < 32; j += 8) t[ty+j][tx] = v[(size_t)(t0 + ty + j)*NS + n0 + tx];
  __syncthreads();
#pragma unroll
  for (int j = 0; j < 32; j += 8) {
    float x = t[tx][ty+j];
    __half h = __float2half_rn(x);
    __half l = __float2half_rn(x - __half2float(h));
    size_t o = (size_t)(n0 + ty + j) * SEQ + t0 + tx;
    g_vth[o] = h; g_vtl[o] = l;
  }
}
__global__ void k_prep_wpt(const float* __restrict__ Wp) {
  __shared__ float t[32][33];
  int n0 = blockIdx.x * 32, k0 = blockIdx.y * 32;
  int tx = threadIdx.x, ty = threadIdx.y;
#pragma unroll
  for (int j = 0; j < 32; j += 8) {
    int n = n0 + tx;
    t[ty+j][tx] = (n < OUTD) ? Wp[(size_t)(k0 + ty + j)*OUTD + n] : 0.f;
  }
  __syncthreads();
#pragma unroll
  for (int j = 0; j < 32; j += 8) {
    __nv_bfloat16 h, l;
    split16(t[tx][ty+j], h, l);
    size_t o = (size_t)(n0 + ty + j) * NS + k0 + tx;
    g_wph[o] = h; g_wpl[o] = l;
  }
}

// ---------------- QK^T (fp16 1-pass) + fused stats ----------------
__device__ __forceinline__ void qk_epilogue(float* __restrict__ S, int ib, int jb,
                                            int wm, int wn, int lane, float acc[2][8][4]) {
#pragma unroll
  for (int mt = 0; mt < 2; mt++)
#pragma unroll
    for (int nt = 0; nt < 8; nt++)
#pragma unroll
      for (int e = 0; e < 4; e++) acc[mt][nt][e] *= 0.25f;
  int jc = jb * 2 + wn;
#pragma unroll
  for (int mt = 0; mt < 2; mt++) {
    int r0 = ib*128 + wm*32 + mt*16 + (lane >> 2);
    float mx0 = -3.4e38f, mx1 = -3.4e38f;
#pragma unroll
    for (int nt = 0; nt < 8; nt++) {
      mx0 = fmaxf(mx0, fmaxf(acc[mt][nt][0], acc[mt][nt][1]));
      mx1 = fmaxf(mx1, fmaxf(acc[mt][nt][2], acc[mt][nt][3]));
    }
    mx0 = fmaxf(mx0, __shfl_xor_sync(~0u, mx0, 1));
    mx0 = fmaxf(mx0, __shfl_xor_sync(~0u, mx0, 2));
    mx1 = fmaxf(mx1, __shfl_xor_sync(~0u, mx1, 1));
    mx1 = fmaxf(mx1, __shfl_xor_sync(~0u, mx1, 2));
    float s0 = 0.f, s1 = 0.f;
#pragma unroll
    for (int nt = 0; nt < 8; nt++) {
      s0 += __expf(acc[mt][nt][0] - mx0) + __expf(acc[mt][nt][1] - mx0);
      s1 += __expf(acc[mt][nt][2] - mx1) + __expf(acc[mt][nt][3] - mx1);
    }
    s0 += __shfl_xor_sync(~0u, s0, 1); s0 += __shfl_xor_sync(~0u, s0, 2);
    s1 += __shfl_xor_sync(~0u, s1, 1); s1 += __shfl_xor_sync(~0u, s1, 2);
    if ((lane & 3) == 0) {
      g_tmax[(size_t)jc*SEQ + r0] = mx0;     g_tsum[(size_t)jc*SEQ + r0] = s0;
      g_tmax[(size_t)jc*SEQ + r0 + 8] = mx1; g_tsum[(size_t)jc*SEQ + r0 + 8] = s1;
    }
    int colb = jb*128 + wn*64 + 2*(lane & 3);
#pragma unroll
    for (int nt = 0; nt < 8; nt++) {
      *(float2*)(S + (size_t)r0*SEQ + colb + nt*8)     = make_float2(acc[mt][nt][0], acc[mt][nt][1]);
      *(float2*)(S + (size_t)(r0+8)*SEQ + colb + nt*8) = make_float2(acc[mt][nt][2], acc[mt][nt][3]);
    }
  }
}

__global__ __launch_bounds__(256) void k_qk_mma(float* __restrict__ S) {
  extern __shared__ char dsm[];
  uint32_t sb = smem_u32(dsm);
  int tid = threadIdx.x, lane = tid & 31, wid = tid >> 5;
  int wm = wid & 3, wn = wid >> 2;
  int ib = blockIdx.x, jb0 = blockIdx.y * 2, jb1 = jb0 + 1;

  load_tile(sb + QKA,  g_qh + (size_t)ib*128*NS, NS, tid);
  load_tile(sb + QKB0, g_kh + (size_t)jb0*128*NS, NS, tid);
  CP_COMMIT();
  load_tile(sb + QKB1, g_kh + (size_t)jb1*128*NS, NS, tid);
  CP_COMMIT();
  CP_WAIT1();
  __syncthreads();
  {
    float acc[2][8][4] = {};
    gemm_pass_h(sb + QKA, sb + QKB0, lane, wm, wn, acc);
    qk_epilogue(S, ib, jb0, wm, wn, lane, acc);
  }
  CP_WAIT0();
  __syncthreads();
  {
    float acc[2][8][4] = {};
    gemm_pass_h(sb + QKA, sb + QKB1, lane, wm, wn, acc);
    qk_epilogue(S, ib, jb1, wm, wn, lane, acc);
  }
}

__global__ void k_combine() {
  int row = blockIdx.x * 256 + threadIdx.x;
  float mx = -3.4e38f;
  for (int j = 0; j < 128; j++) mx = fmaxf(mx, g_tmax[(size_t)j*SEQ + row]);
  float s = 0.f;
  for (int j = 0; j < 128; j++) s += g_tsum[(size_t)j*SEQ + row] * __expf(g_tmax[(size_t)j*SEQ + row] - mx);
  g_RM[row] = mx;
  g_RSI[row] = 1.0f / s;
}

// ---------------- softmax + attn write + attn@V (fp16 2-pass, double-buffered V) ----------------
__global__ __launch_bounds__(256) void k_ctx_mma(float* __restrict__ S) {
  extern __shared__ char dsm[];
  uint32_t sb = smem_u32(dsm);
  int tid = threadIdx.x, lane = tid & 31, wid = tid >> 5;
  int wm = wid & 3, wn = wid >> 2;
  int ib = blockIdx.x, sp = blockIdx.y;

  int crow = tid >> 1;
  int cbase = (tid & 1) * 64;
  float m = g_RM[ib*128 + crow];
  float li = g_RSI[ib*128 + crow];

  load_tile(sb + CVH0, g_vth + sp*1024, SEQ, tid);
  load_tile(sb + CVL0, g_vtl + sp*1024, SEQ, tid);
  CP_COMMIT();

  float acc[2][8][4] = {};
  for (int c = 0; c < 8; c++) {
    uint32_t bH = (c & 1) ? CVH1 : CVH0;
    uint32_t bL = (c & 1) ? CVL1 : CVL0;
    if (c < 7) {
      uint32_t nH = (c & 1) ? CVH0 : CVH1;
      uint32_t nL = (c & 1) ? CVL0 : CVL1;
      int kn = sp*1024 + (c+1)*128;
      load_tile(sb + nH, g_vth + kn, SEQ, tid);
      load_tile(sb + nL, g_vtl + kn, SEQ, tid);
      CP_COMMIT();
    }
    int k0 = sp*1024 + c*128;
    float2* srow = (float2*)(S + (size_t)(ib*128 + crow)*SEQ + k0 + cbase);
    uint32_t abase = sb + CTA_A + (uint32_t)((crow * TPAD + cbase) << 1);
#pragma unroll 8
    for (int i = 0; i < 32; i++) {
      float2 s2 = srow[i];
      float a0 = __expf(s2.x - m) * li;
      float a1 = __expf(s2.y - m) * li;
      srow[i] = make_float2(a0, a1);
      sts32(abase + i*4, packh(__float2half_rn(a0), __float2half_rn(a1)));
    }
    if (c < 7) CP_WAIT1(); else CP_WAIT0();
    __syncthreads();
    gemm_pass_h(sb + CTA_A, sb + bH, lane, wm, wn, acc);
    gemm_pass_h(sb + CTA_A, sb + bL, lane, wm, wn, acc);
    __syncthreads();
  }
#pragma unroll
  for (int mt = 0; mt < 2; mt++) {
    int r0 = ib*128 + wm*32 + mt*16 + (lane >> 2);
    int colb = wn*64 + 2*(lane & 3);
#pragma unroll
    for (int nt = 0; nt < 8; nt++) {
      *(float2*)(g_ctxp + ((size_t)sp*SEQ + r0)*NS + colb + nt*8)     = make_float2(acc[mt][nt][0], acc[mt][nt][1]);
      *(float2*)(g_ctxp + ((size_t)sp*SEQ + r0 + 8)*NS + colb + nt*8) = make_float2(acc[mt][nt][2], acc[mt][nt][3]);
    }
  }
}

__global__ void k_ctxred() {
  size_t idx = (size_t)blockIdx.x * 256 + threadIdx.x;
  float acc = 0.f;
#pragma unroll
  for (int s = 0; s < 8; s++) acc += g_ctxp[(size_t)s*SEQ*NS + idx];
  __nv_bfloat16 h, l;
  split16(acc, h, l);
  g_ch[idx] = h; g_clo[idx] = l;
}

// ---------------- out = ctx @ Wp + bp (bf16 3-pass) ----------------
__global__ __launch_bounds__(256) void k_out_mma(float* __restrict__ out, const float* __restrict__ bp) {
  extern __shared__ char dsm[];
  uint32_t sb = smem_u32(dsm);
  int tid = threadIdx.x, lane = tid & 31, wid = tid >> 5;
  int wm = wid & 3, wn = wid >> 2;
  int ib = blockIdx.x, cb = blockIdx.y;

  load_tile(sb + OAH, g_ch  + (size_t)ib*128*NS, NS, tid);
  load_tile(sb + OAL, g_clo + (size_t)ib*128*NS, NS, tid);
  load_tile(sb + OBH, g_wph + (size_t)cb*128*NS, NS, tid);
  load_tile(sb + OBL, g_wpl + (size_t)cb*128*NS, NS, tid);
  CP_COMMIT(); CP_WAIT0();
  __syncthreads();

  float acc[2][8][4] = {};
  gemm3v(sb + OAH, sb + OAL, sb + OBH, sb + OBL, lane, wm, wn, acc);

#pragma unroll
  for (int mt = 0; mt < 2; mt++) {
    int r0 = ib*128 + wm*32 + mt*16 + (lane >> 2);
#pragma unroll
    for (int nt = 0; nt < 8; nt++) {
      int gc = cb*128 + wn*64 + nt*8 + 2*(lane & 3);
      if (gc + 1 < OUTD) {
        out[(size_t)r0*OUTD + gc]         = acc[mt][nt][0] + bp[gc];
        out[(size_t)r0*OUTD + gc + 1]     = acc[mt][nt][1] + bp[gc + 1];
        out[(size_t)(r0+8)*OUTD + gc]     = acc[mt][nt][2] + bp[gc];
        out[(size_t)(r0+8)*OUTD + gc + 1] = acc[mt][nt][3] + bp[gc + 1];
      } else if (gc < OUTD) {
        out[(size_t)r0*OUTD + gc]     = acc[mt][nt][0] + bp[gc];
        out[(size_t)(r0+8)*OUTD + gc] = acc[mt][nt][2] + bp[gc];
      }
    }
  }
}

// ---------------- launch ----------------
extern "C" void kernel_launch(void* const* d_in, const int* in_sizes, int n_in,
                              void* d_out, int out_size) {
  const float* q  = (const float*)d_in[0];
  const float* kk = (const float*)d_in[1];
  const float* vv = (const float*)d_in[2];
  const float* GA = (const float*)d_in[3];
  const float* GB = (const float*)d_in[4];
  const float* Wp = (const float*)d_in[5];
  const float* bp = (const float*)d_in[6];
  float* out = (float*)d_out;

  cudaFuncSetAttribute(k_powers_f,    cudaFuncAttributeMaxDynamicSharedMemorySize, POW_SM);
  cudaFuncSetAttribute(k_localconv_h, cudaFuncAttributeMaxDynamicSharedMemorySize, SCAN2_SM);
  cudaFuncSetAttribute(k_boundary_h,  cudaFuncAttributeMaxDynamicSharedMemorySize, SCAN2_SM);
  cudaFuncSetAttribute(k_propagate_h, cudaFuncAttributeMaxDynamicSharedMemorySize, SCAN2_SM);
  cudaFuncSetAttribute(k_qk_mma,      cudaFuncAttributeMaxDynamicSharedMemorySize, QK_SM);
  cudaFuncSetAttribute(k_ctx_mma,     cudaFuncAttributeMaxDynamicSharedMemorySize, CTX_SM);
  cudaFuncSetAttribute(k_out_mma,     cudaFuncAttributeMaxDynamicSharedMemorySize, GEMM_SM);

  float* pFB;
  cudaGetSymbolAddress((void**)&pFB, g_attn_fb);
  float* S = (out_size >= (int)((size_t)SEQ*OUTD + (size_t)SEQ*SEQ)) ? out + (size_t)SEQ*OUTD : pFB;

  k_prep_wpt<<<dim3(32, 4), dim3(32, 8)>>>(Wp);          // 0
  k_init<<<128, 128>>>(GA);                              // 1
  k_prep_small<<<1, 256>>>(GB);                          // 2
  k_powers_f<<<191, 256, POW_SM>>>(GB);                  // 3 ← ncu profiled slot
  k_localconv_h<<<dim3(64, 3), 256, SCAN2_SM>>>(q, kk, vv);
  k_boundary_h<<<dim3(64, 2), 256, SCAN2_SM>>>();
  k_propagate_h<<<dim3(128, 2), 256, SCAN2_SM>>>();
  k_prep_qk<<<8192, 256>>>();
  k_prep_vt<<<dim3(256, 4), dim3(32, 8)>>>();
  k_qk_mma<<<dim3(64, 32), 256, QK_SM>>>(S);
  k_combine<<<32, 256>>>();
  k_ctx_mma<<<dim3(64, 8), 256, CTX_SM>>>(S);
  k_ctxred<<<4096, 256>>>();
  k_out_mma<<<dim3(64, 8), 256, GEMM_SM>>>(out, bp);
}